// round 1
// baseline (speedup 1.0000x reference)
#include <cuda_runtime.h>
#include <cuda_bf16.h>

#define NN 50000
#define EE 800000

// ---------------- scratch (no allocations allowed) ----------------
__device__ float g_feat[NN * 128];   // per-layer fc output [N, H*D]
__device__ float g_agg [NN * 128];   // aggregated output (init to bias)
__device__ float g_x   [NN * 64];    // layer-1 output after lin+relu
__device__ float g_el  [NN * 2];
__device__ float g_er  [NN * 2];
__device__ float g_z   [NN * 2];
__device__ float g_e   [EE * 2];     // per-edge exp(leaky(el+er))

// ---------------- helpers ----------------
__device__ __forceinline__ void red_add_v4(float* p, float4 v) {
    asm volatile("red.global.add.v4.f32 [%0], {%1,%2,%3,%4};"
                 :: "l"(p), "f"(v.x), "f"(v.y), "f"(v.z), "f"(v.w)
                 : "memory");
}

// ---------------- GEMM: C[n,M] = A[n,K] @ W[K,M] (+bias, relu) ----------------
// 64x64 tile per block, 256 threads, 4x4 register tile each.
__global__ void gemm_kernel(const float* __restrict__ A, const float* __restrict__ W,
                            const float* __restrict__ bias, float* __restrict__ C,
                            int n, int K, int M, int relu) {
    __shared__ float As[16][68];   // [kk][row]  (transposed for float4 reads)
    __shared__ float Ws[16][68];   // [kk][col]
    int tid = threadIdx.x;
    int tx = tid & 15, ty = tid >> 4;
    int r0 = blockIdx.x * 64, c0 = blockIdx.y * 64;
    float acc[4][4] = {};

    for (int kc = 0; kc < K; kc += 16) {
        // load A tile: rows r0..+63, cols kc..+15 -> As[kk][row]
        {
            int kk = tid & 15, rr = tid >> 4;
            #pragma unroll
            for (int i = 0; i < 4; i++) {
                int row = r0 + rr + i * 16;
                As[kk][rr + i * 16] = (row < n) ? A[row * K + kc + kk] : 0.f;
            }
        }
        // load W tile: Ws[kk][c] = W[(kc+kk)*M + c0+c]
        {
            int c = tid & 63, k2 = tid >> 6;
            #pragma unroll
            for (int i = 0; i < 4; i++)
                Ws[k2 + i * 4][c] = W[(kc + k2 + i * 4) * M + c0 + c];
        }
        __syncthreads();
        #pragma unroll
        for (int k = 0; k < 16; k++) {
            float4 a4 = *(const float4*)&As[k][ty * 4];
            float4 w4 = *(const float4*)&Ws[k][tx * 4];
            float av[4] = {a4.x, a4.y, a4.z, a4.w};
            float wv[4] = {w4.x, w4.y, w4.z, w4.w};
            #pragma unroll
            for (int i = 0; i < 4; i++)
                #pragma unroll
                for (int j = 0; j < 4; j++)
                    acc[i][j] = fmaf(av[i], wv[j], acc[i][j]);
        }
        __syncthreads();
    }

    #pragma unroll
    for (int i = 0; i < 4; i++) {
        int row = r0 + ty * 4 + i;
        if (row >= n) continue;
        #pragma unroll
        for (int j = 0; j < 4; j++) {
            int col = c0 + tx * 4 + j;
            float v = acc[i][j] + (bias ? bias[col] : 0.f);
            if (relu) v = fmaxf(v, 0.f);
            C[row * M + col] = v;
        }
    }
}

// ---------------- per-node attention logits: el/er [N,2] ----------------
// one warp per node; feat row = 128 floats; al/ar = [2,64] flattened.
__global__ void elr_kernel(const float* __restrict__ feat,
                           const float* __restrict__ al, const float* __restrict__ ar) {
    int w = (blockIdx.x * blockDim.x + threadIdx.x) >> 5;
    int lane = threadIdx.x & 31;
    if (w >= NN) return;
    const float* f = feat + w * 128;
    float f0 = f[lane], f1 = f[lane + 32], f2 = f[lane + 64], f3 = f[lane + 96];
    float e0 = f0 * al[lane]      + f1 * al[lane + 32];
    float e1 = f2 * al[lane + 64] + f3 * al[lane + 96];
    float r0 = f0 * ar[lane]      + f1 * ar[lane + 32];
    float r1 = f2 * ar[lane + 64] + f3 * ar[lane + 96];
    #pragma unroll
    for (int o = 16; o > 0; o >>= 1) {
        e0 += __shfl_xor_sync(0xffffffffu, e0, o);
        e1 += __shfl_xor_sync(0xffffffffu, e1, o);
        r0 += __shfl_xor_sync(0xffffffffu, r0, o);
        r1 += __shfl_xor_sync(0xffffffffu, r1, o);
    }
    if (lane == 0) {
        g_el[w * 2] = e0; g_el[w * 2 + 1] = e1;
        g_er[w * 2] = r0; g_er[w * 2 + 1] = r1;
    }
}

// ---------------- init: agg = bias (broadcast), z = 0 ----------------
__global__ void init_kernel(const float* __restrict__ bias) {
    int i = blockIdx.x * blockDim.x + threadIdx.x;
    if (i < NN * 128) g_agg[i] = bias[i & 127];
    if (i < NN * 2)   g_z[i] = 0.f;
}

// ---------------- edge pass 1: ex = exp(leaky(el[src]+er[dst])); z[dst]+=ex ----
// (softmax is shift-invariant; logits are bounded so no segment_max needed)
__global__ void edge_ex_kernel(const int* __restrict__ src, const int* __restrict__ dst) {
    int e = blockIdx.x * blockDim.x + threadIdx.x;
    if (e >= EE) return;
    int s = src[e], d = dst[e];
    float2 l = *(const float2*)(g_el + 2 * s);
    float2 r = *(const float2*)(g_er + 2 * d);
    float v0 = l.x + r.x; v0 = v0 > 0.f ? v0 : 0.2f * v0;
    float v1 = l.y + r.y; v1 = v1 > 0.f ? v1 : 0.2f * v1;
    float x0 = __expf(v0), x1 = __expf(v1);
    float2 ex; ex.x = x0; ex.y = x1;
    *(float2*)(g_e + 2 * e) = ex;
    atomicAdd(&g_z[2 * d],     x0);
    atomicAdd(&g_z[2 * d + 1], x1);
}

// ---------------- edge pass 2: agg[dst] += (ex/z[dst]) * feat[src] ----------------
// one warp per edge; 32 lanes x float4 = 128-float row; vector reductions.
__global__ void edge_agg_kernel(const int* __restrict__ src, const int* __restrict__ dst) {
    int w = (blockIdx.x * blockDim.x + threadIdx.x) >> 5;
    int lane = threadIdx.x & 31;
    if (w >= EE) return;
    int s = src[w], d = dst[w];
    float2 ex = *(const float2*)(g_e + 2 * w);
    float2 zz = *(const float2*)(g_z + 2 * d);
    float a0 = __fdividef(ex.x, zz.x);
    float a1 = __fdividef(ex.y, zz.y);
    float a = (lane < 16) ? a0 : a1;
    float4 f = ((const float4*)g_feat)[s * 32 + lane];
    float4 v; v.x = a * f.x; v.y = a * f.y; v.z = a * f.z; v.w = a * f.w;
    red_add_v4((float*)(((float4*)g_agg) + d * 32 + lane), v);
}

// ---------------- host ----------------
extern "C" void kernel_launch(void* const* d_in, const int* in_sizes, int n_in,
                              void* d_out, int out_size) {
    const float* h     = (const float*)d_in[0];
    const int*   src   = (const int*)d_in[1];
    const int*   dst   = (const int*)d_in[2];
    const float* W1    = (const float*)d_in[3];
    const float* al1   = (const float*)d_in[4];
    const float* ar1   = (const float*)d_in[5];
    const float* b1    = (const float*)d_in[6];
    const float* lin1W = (const float*)d_in[7];
    const float* lin1b = (const float*)d_in[8];
    const float* W2    = (const float*)d_in[9];
    const float* al2   = (const float*)d_in[10];
    const float* ar2   = (const float*)d_in[11];
    const float* b2    = (const float*)d_in[12];
    const float* lin2W = (const float*)d_in[13];
    const float* lin2b = (const float*)d_in[14];
    float* out = (float*)d_out;

    float *feat, *agg, *x;
    cudaGetSymbolAddress((void**)&feat, g_feat);
    cudaGetSymbolAddress((void**)&agg,  g_agg);
    cudaGetSymbolAddress((void**)&x,    g_x);

    const int ROWT = (NN + 63) / 64;              // 782 row tiles
    const int ELR_G = (NN * 32 + 255) / 256;      // one warp per node
    const int INIT_G = (NN * 128 + 255) / 256;
    const int EX_G = (EE + 255) / 256;
    const int AGG_G = (EE * 32 + 255) / 256;      // one warp per edge

    // ---- layer 1 ----
    gemm_kernel<<<dim3(ROWT, 2), 256>>>(h, W1, nullptr, feat, NN, 128, 128, 0);
    elr_kernel<<<ELR_G, 256>>>(feat, al1, ar1);
    init_kernel<<<INIT_G, 256>>>(b1);
    edge_ex_kernel<<<EX_G, 256>>>(src, dst);
    edge_agg_kernel<<<AGG_G, 256>>>(src, dst);
    gemm_kernel<<<dim3(ROWT, 1), 256>>>(agg, lin1W, lin1b, x, NN, 128, 64, 1);

    // ---- layer 2 ----
    gemm_kernel<<<dim3(ROWT, 2), 256>>>(x, W2, nullptr, feat, NN, 64, 128, 0);
    elr_kernel<<<ELR_G, 256>>>(feat, al2, ar2);
    init_kernel<<<INIT_G, 256>>>(b2);
    edge_ex_kernel<<<EX_G, 256>>>(src, dst);
    edge_agg_kernel<<<AGG_G, 256>>>(src, dst);
    gemm_kernel<<<dim3(ROWT, 1), 256>>>(agg, lin2W, lin2b, out, NN, 128, 64, 0);
}

// round 3
// speedup vs baseline: 2.1280x; 2.1280x over previous
#include <cuda_runtime.h>
#include <cuda_bf16.h>

#define NN 50000
#define EE 800000

// ---------------- scratch (no allocations allowed) ----------------
__device__ float g_feat[NN * 128];   // per-layer fc output [N, H*D]
__device__ float g_agg [NN * 128];   // conv output (softmax-agg + bias)
__device__ float g_x   [NN * 64];    // layer-1 output after lin+relu
__device__ float g_el  [NN * 2];
__device__ float g_er  [NN * 2];
// CSR scratch
__device__ int g_cnt[NN];
__device__ int g_tmp[NN];            // per-block inclusive scans
__device__ int g_rowptr[NN + 1];
__device__ int g_wptr[NN];
__device__ int g_srcs[EE];           // src node per dst-sorted edge
__device__ int g_bsum[128];

// ---------------- helpers ----------------
__device__ __forceinline__ unsigned f2tf(float x) {
    unsigned u;
    asm("cvt.rna.tf32.f32 %0, %1;" : "=r"(u) : "f"(x));
    return u;
}

// ======================= tf32 tensor-core GEMM =======================
// C[n,M] = A[n,K] @ W[K,M] (+bias, +relu).  Block: 128 rows x 64 cols,
// 256 threads = 8 warps, each warp does 16 rows x 64 cols via mma.m16n8k8.
template<int K, int M>
__global__ void __launch_bounds__(256)
gemm_mma(const float* __restrict__ A, const float* __restrict__ W,
         const float* __restrict__ bias, float* __restrict__ C,
         int n, int relu) {
    __shared__ float As[128][36];  // [row][k], pad 36 -> conflict-free frags
    __shared__ float Ws[32][72];   // [k][col],  pad 72 -> conflict-free frags
    int tid  = threadIdx.x;
    int lane = tid & 31, warp = tid >> 5;
    int g = lane >> 2, t4 = lane & 3;
    int r0 = blockIdx.x * 128;
    int c0 = blockIdx.y * 64;

    float acc[8][4];
    #pragma unroll
    for (int i = 0; i < 8; i++)
        #pragma unroll
        for (int j = 0; j < 4; j++) acc[i][j] = 0.f;

    for (int kc = 0; kc < K; kc += 32) {
        // stage A tile 128x32 (tf32-rounded)
        #pragma unroll
        for (int it = 0; it < 4; it++) {
            int f4 = tid + it * 256;           // 0..1023
            int row = f4 >> 3, kq = (f4 & 7) * 4;
            float4 v = make_float4(0.f, 0.f, 0.f, 0.f);
            if (r0 + row < n) v = *(const float4*)&A[(size_t)(r0 + row) * K + kc + kq];
            As[row][kq + 0] = __uint_as_float(f2tf(v.x));
            As[row][kq + 1] = __uint_as_float(f2tf(v.y));
            As[row][kq + 2] = __uint_as_float(f2tf(v.z));
            As[row][kq + 3] = __uint_as_float(f2tf(v.w));
        }
        // stage W tile 32x64 (tf32-rounded)
        #pragma unroll
        for (int it = 0; it < 2; it++) {
            int f4 = tid + it * 256;           // 0..511
            int k = f4 >> 4, cq = (f4 & 15) * 4;
            float4 v = *(const float4*)&W[(size_t)(kc + k) * M + c0 + cq];
            Ws[k][cq + 0] = __uint_as_float(f2tf(v.x));
            Ws[k][cq + 1] = __uint_as_float(f2tf(v.y));
            Ws[k][cq + 2] = __uint_as_float(f2tf(v.z));
            Ws[k][cq + 3] = __uint_as_float(f2tf(v.w));
        }
        __syncthreads();

        int wr = warp * 16;
        #pragma unroll
        for (int kk = 0; kk < 4; kk++) {
            unsigned a0 = __float_as_uint(As[wr + g    ][kk * 8 + t4    ]);
            unsigned a1 = __float_as_uint(As[wr + g + 8][kk * 8 + t4    ]);
            unsigned a2 = __float_as_uint(As[wr + g    ][kk * 8 + t4 + 4]);
            unsigned a3 = __float_as_uint(As[wr + g + 8][kk * 8 + t4 + 4]);
            #pragma unroll
            for (int nt = 0; nt < 8; nt++) {
                unsigned b0 = __float_as_uint(Ws[kk * 8 + t4    ][nt * 8 + g]);
                unsigned b1 = __float_as_uint(Ws[kk * 8 + t4 + 4][nt * 8 + g]);
                asm volatile(
                    "mma.sync.aligned.m16n8k8.row.col.f32.tf32.tf32.f32 "
                    "{%0,%1,%2,%3}, {%4,%5,%6,%7}, {%8,%9}, {%0,%1,%2,%3};"
                    : "+f"(acc[nt][0]), "+f"(acc[nt][1]),
                      "+f"(acc[nt][2]), "+f"(acc[nt][3])
                    : "r"(a0), "r"(a1), "r"(a2), "r"(a3), "r"(b0), "r"(b1));
            }
        }
        __syncthreads();
    }

    // epilogue
    int wr = warp * 16;
    #pragma unroll
    for (int nt = 0; nt < 8; nt++) {
        int col = c0 + nt * 8 + t4 * 2;
        float bx = 0.f, by = 0.f;
        if (bias) { bx = bias[col]; by = bias[col + 1]; }
        float v0 = acc[nt][0] + bx, v1 = acc[nt][1] + by;
        float v2 = acc[nt][2] + bx, v3 = acc[nt][3] + by;
        if (relu) {
            v0 = fmaxf(v0, 0.f); v1 = fmaxf(v1, 0.f);
            v2 = fmaxf(v2, 0.f); v3 = fmaxf(v3, 0.f);
        }
        int row0 = r0 + wr + g, row1 = row0 + 8;
        if (row0 < n) *(float2*)&C[(size_t)row0 * M + col] = make_float2(v0, v1);
        if (row1 < n) *(float2*)&C[(size_t)row1 * M + col] = make_float2(v2, v3);
    }
}

// ---------------- per-node attention logits: el/er [N,2] ----------------
__global__ void __launch_bounds__(256)
elr_kernel(const float* __restrict__ feat,
           const float* __restrict__ al, const float* __restrict__ ar) {
    int w = (blockIdx.x * blockDim.x + threadIdx.x) >> 5;
    int lane = threadIdx.x & 31;
    if (w >= NN) return;
    const float* f = feat + (size_t)w * 128;
    float f0 = f[lane], f1 = f[lane + 32], f2 = f[lane + 64], f3 = f[lane + 96];
    float e0 = f0 * al[lane]      + f1 * al[lane + 32];
    float e1 = f2 * al[lane + 64] + f3 * al[lane + 96];
    float r0 = f0 * ar[lane]      + f1 * ar[lane + 32];
    float r1 = f2 * ar[lane + 64] + f3 * ar[lane + 96];
    #pragma unroll
    for (int o = 16; o > 0; o >>= 1) {
        e0 += __shfl_xor_sync(0xffffffffu, e0, o);
        e1 += __shfl_xor_sync(0xffffffffu, e1, o);
        r0 += __shfl_xor_sync(0xffffffffu, r0, o);
        r1 += __shfl_xor_sync(0xffffffffu, r1, o);
    }
    if (lane == 0) {
        g_el[w * 2] = e0; g_el[w * 2 + 1] = e1;
        g_er[w * 2] = r0; g_er[w * 2 + 1] = r1;
    }
}

// ======================= CSR build =======================
__global__ void k_zero() {
    int i = blockIdx.x * blockDim.x + threadIdx.x;
    if (i < NN) g_cnt[i] = 0;
}
__global__ void k_hist(const int* __restrict__ dst) {
    int e = blockIdx.x * blockDim.x + threadIdx.x;
    if (e < EE) atomicAdd(&g_cnt[dst[e]], 1);
}
__global__ void k_scan1() {   // 98 blocks x 512
    __shared__ int s[512];
    int i = blockIdx.x * 512 + threadIdx.x;
    int v = (i < NN) ? g_cnt[i] : 0;
    s[threadIdx.x] = v;
    __syncthreads();
    for (int off = 1; off < 512; off <<= 1) {
        int t = (threadIdx.x >= off) ? s[threadIdx.x - off] : 0;
        __syncthreads();
        s[threadIdx.x] += t;
        __syncthreads();
    }
    if (i < NN) g_tmp[i] = s[threadIdx.x];
    if (threadIdx.x == 511) g_bsum[blockIdx.x] = s[511];
}
__global__ void k_scan2() {   // 1 block x 128 scans the 98 block sums
    __shared__ int s[128];
    int v = (threadIdx.x < 98) ? g_bsum[threadIdx.x] : 0;
    s[threadIdx.x] = v;
    __syncthreads();
    for (int off = 1; off < 128; off <<= 1) {
        int t = (threadIdx.x >= off) ? s[threadIdx.x - off] : 0;
        __syncthreads();
        s[threadIdx.x] += t;
        __syncthreads();
    }
    if (threadIdx.x < 98) g_bsum[threadIdx.x] = s[threadIdx.x] - v;  // exclusive
}
__global__ void k_scan3() {
    int i = blockIdx.x * blockDim.x + threadIdx.x;
    if (i >= NN) return;
    int off = g_bsum[i >> 9];
    int excl = g_tmp[i] - g_cnt[i] + off;
    g_rowptr[i] = excl;
    g_wptr[i]   = excl;
    if (i == NN - 1) g_rowptr[NN] = g_tmp[i] + off;
}
__global__ void k_scatter(const int* __restrict__ src, const int* __restrict__ dst) {
    int e = blockIdx.x * blockDim.x + threadIdx.x;
    if (e >= EE) return;
    int p = atomicAdd(&g_wptr[dst[e]], 1);
    g_srcs[p] = src[e];
}

// ======================= fused edge-softmax + aggregation =======================
// one warp per dst node: single pass; un-normalized accumulate, divide at end.
__global__ void __launch_bounds__(256)
gat_agg(const float* __restrict__ bias, float* __restrict__ outp) {
    __shared__ float2 s_ex[8][32];
    __shared__ int    s_src[8][32];
    int lane = threadIdx.x & 31, w = threadIdx.x >> 5;
    int d = blockIdx.x * 8 + w;
    if (d >= NN) return;
    int beg = g_rowptr[d], end = g_rowptr[d + 1];
    float2 er2 = *(const float2*)(g_er + 2 * d);
    const float4* feat4 = (const float4*)g_feat;

    float4 acc = make_float4(0.f, 0.f, 0.f, 0.f);
    float z0 = 0.f, z1 = 0.f;

    for (int c = beg; c < end; c += 32) {
        int idx = c + lane;
        bool valid = idx < end;
        int s = valid ? g_srcs[idx] : 0;
        float2 el2 = *(const float2*)(g_el + 2 * s);
        float e0 = el2.x + er2.x; e0 = e0 > 0.f ? e0 : 0.2f * e0;
        float e1 = el2.y + er2.y; e1 = e1 > 0.f ? e1 : 0.2f * e1;
        float x0 = valid ? __expf(e0) : 0.f;
        float x1 = valid ? __expf(e1) : 0.f;
        z0 += x0; z1 += x1;
        s_ex[w][lane]  = make_float2(x0, x1);
        s_src[w][lane] = s;
        __syncwarp();
        int m = min(32, end - c);
        for (int j = 0; j < m; j++) {
            int sj = s_src[w][j];
            float2 exj = s_ex[w][j];
            float wgt = (lane < 16) ? exj.x : exj.y;
            float4 f = feat4[(size_t)sj * 32 + lane];
            acc.x = fmaf(wgt, f.x, acc.x);
            acc.y = fmaf(wgt, f.y, acc.y);
            acc.z = fmaf(wgt, f.z, acc.z);
            acc.w = fmaf(wgt, f.w, acc.w);
        }
        __syncwarp();
    }
    #pragma unroll
    for (int o = 16; o > 0; o >>= 1) {
        z0 += __shfl_xor_sync(0xffffffffu, z0, o);
        z1 += __shfl_xor_sync(0xffffffffu, z1, o);
    }
    float z = (lane < 16) ? z0 : z1;
    float ia = (z > 0.f) ? __fdividef(1.f, z) : 0.f;
    float4 b4 = ((const float4*)bias)[lane];
    float4 o4;
    o4.x = fmaf(acc.x, ia, b4.x);
    o4.y = fmaf(acc.y, ia, b4.y);
    o4.z = fmaf(acc.z, ia, b4.z);
    o4.w = fmaf(acc.w, ia, b4.w);
    ((float4*)outp)[(size_t)d * 32 + lane] = o4;
}

// ======================= host =======================
extern "C" void kernel_launch(void* const* d_in, const int* in_sizes, int n_in,
                              void* d_out, int out_size) {
    const float* h     = (const float*)d_in[0];
    const int*   src   = (const int*)d_in[1];
    const int*   dst   = (const int*)d_in[2];
    const float* W1    = (const float*)d_in[3];
    const float* al1   = (const float*)d_in[4];
    const float* ar1   = (const float*)d_in[5];
    const float* b1    = (const float*)d_in[6];
    const float* lin1W = (const float*)d_in[7];
    const float* lin1b = (const float*)d_in[8];
    const float* W2    = (const float*)d_in[9];
    const float* al2   = (const float*)d_in[10];
    const float* ar2   = (const float*)d_in[11];
    const float* b2    = (const float*)d_in[12];
    const float* lin2W = (const float*)d_in[13];
    const float* lin2b = (const float*)d_in[14];
    float* out = (float*)d_out;

    float *feat, *agg, *x;
    cudaGetSymbolAddress((void**)&feat, g_feat);
    cudaGetSymbolAddress((void**)&agg,  g_agg);
    cudaGetSymbolAddress((void**)&x,    g_x);

    const int ROWT  = (NN + 127) / 128;           // 391
    const int NB    = (NN + 255) / 256;           // 196
    const int EB    = (EE + 255) / 256;           // 3125
    const int WARPB = (NN * 32 + 255) / 256;      // 6250 (one warp per node)

    // ---- CSR build (dst-sorted edges) ----
    k_zero<<<NB, 256>>>();
    k_hist<<<EB, 256>>>(dst);
    k_scan1<<<98, 512>>>();
    k_scan2<<<1, 128>>>();
    k_scan3<<<NB, 256>>>();
    k_scatter<<<EB, 256>>>(src, dst);

    // ---- layer 1 ----
    gemm_mma<128, 128><<<dim3(ROWT, 2), 256>>>(h, W1, nullptr, feat, NN, 0);
    elr_kernel<<<WARPB, 256>>>(feat, al1, ar1);
    gat_agg<<<WARPB, 256>>>(b1, agg);
    gemm_mma<128, 64><<<dim3(ROWT, 1), 256>>>(agg, lin1W, lin1b, x, NN, 1);

    // ---- layer 2 ----
    gemm_mma<64, 128><<<dim3(ROWT, 2), 256>>>(x, W2, nullptr, feat, NN, 0);
    elr_kernel<<<WARPB, 256>>>(feat, al2, ar2);
    gat_agg<<<WARPB, 256>>>(b2, agg);
    gemm_mma<128, 64><<<dim3(ROWT, 1), 256>>>(agg, lin2W, lin2b, out, NN, 0);
}

// round 6
// speedup vs baseline: 2.3679x; 1.1127x over previous
#include <cuda_runtime.h>
#include <cuda_bf16.h>

#define NN 50000
#define EE 800000

// ---------------- scratch (no allocations allowed) ----------------
__device__ float g_feat[NN * 128];
__device__ float g_agg [NN * 128];
__device__ float g_x   [NN * 64];
__device__ float g_el  [NN * 2];
__device__ float g_er  [NN * 2];
// CSR scratch
__device__ int g_cnt[NN];
__device__ int g_tmp[NN];
__device__ int g_rowptr[NN + 1];
__device__ int g_wptr[NN];
__device__ int g_srcs[EE];
__device__ int g_bsum[128];

// ---------------- helpers ----------------
__device__ __forceinline__ unsigned f2tf(float x) {
    unsigned u;
    asm("cvt.rna.tf32.f32 %0, %1;" : "=r"(u) : "f"(x));
    return u;
}

// ======================= tf32 tensor-core GEMM (+ fused attn logits) ==========
// C[n,M] = A[n,K] @ W[K,M] (+bias,+relu). 128x64 tile, 256 thr, m16n8k8 mma.
// If ATTN: M==128, blockIdx.y == head; epilogue also emits g_el/g_er.
template<int K, int M, bool ATTN>
__global__ void __launch_bounds__(256)
gemm_mma(const float* __restrict__ A, const float* __restrict__ W,
         const float* __restrict__ bias, float* __restrict__ C,
         int n, int relu, const float* __restrict__ al, const float* __restrict__ ar) {
    __shared__ float As[128][36];
    __shared__ float Ws[32][72];
    int tid  = threadIdx.x;
    int lane = tid & 31, warp = tid >> 5;
    int g = lane >> 2, t4 = lane & 3;
    int r0 = blockIdx.x * 128;
    int c0 = blockIdx.y * 64;

    float acc[8][4];
    #pragma unroll
    for (int i = 0; i < 8; i++)
        #pragma unroll
        for (int j = 0; j < 4; j++) acc[i][j] = 0.f;

    // register prefetch buffers
    float4 va[4], vw[2];

    // preload kc = 0
    #pragma unroll
    for (int it = 0; it < 4; it++) {
        int f4 = tid + it * 256;
        int row = f4 >> 3, kq = (f4 & 7) * 4;
        va[it] = make_float4(0.f, 0.f, 0.f, 0.f);
        if (r0 + row < n) va[it] = *(const float4*)&A[(size_t)(r0 + row) * K + kq];
    }
    #pragma unroll
    for (int it = 0; it < 2; it++) {
        int f4 = tid + it * 256;
        int k = f4 >> 4, cq = (f4 & 15) * 4;
        vw[it] = *(const float4*)&W[(size_t)k * M + c0 + cq];
    }

    for (int kc = 0; kc < K; kc += 32) {
        // commit prefetched tile to smem (tf32-rounded)
        #pragma unroll
        for (int it = 0; it < 4; it++) {
            int f4 = tid + it * 256;
            int row = f4 >> 3, kq = (f4 & 7) * 4;
            As[row][kq + 0] = __uint_as_float(f2tf(va[it].x));
            As[row][kq + 1] = __uint_as_float(f2tf(va[it].y));
            As[row][kq + 2] = __uint_as_float(f2tf(va[it].z));
            As[row][kq + 3] = __uint_as_float(f2tf(va[it].w));
        }
        #pragma unroll
        for (int it = 0; it < 2; it++) {
            int f4 = tid + it * 256;
            int k = f4 >> 4, cq = (f4 & 15) * 4;
            Ws[k][cq + 0] = __uint_as_float(f2tf(vw[it].x));
            Ws[k][cq + 1] = __uint_as_float(f2tf(vw[it].y));
            Ws[k][cq + 2] = __uint_as_float(f2tf(vw[it].z));
            Ws[k][cq + 3] = __uint_as_float(f2tf(vw[it].w));
        }
        __syncthreads();

        // prefetch next slab (overlaps with MMA below)
        if (kc + 32 < K) {
            #pragma unroll
            for (int it = 0; it < 4; it++) {
                int f4 = tid + it * 256;
                int row = f4 >> 3, kq = (f4 & 7) * 4;
                va[it] = make_float4(0.f, 0.f, 0.f, 0.f);
                if (r0 + row < n)
                    va[it] = *(const float4*)&A[(size_t)(r0 + row) * K + kc + 32 + kq];
            }
            #pragma unroll
            for (int it = 0; it < 2; it++) {
                int f4 = tid + it * 256;
                int k = f4 >> 4, cq = (f4 & 15) * 4;
                vw[it] = *(const float4*)&W[(size_t)(kc + 32 + k) * M + c0 + cq];
            }
        }

        int wr = warp * 16;
        #pragma unroll
        for (int kk = 0; kk < 4; kk++) {
            unsigned a0 = __float_as_uint(As[wr + g    ][kk * 8 + t4    ]);
            unsigned a1 = __float_as_uint(As[wr + g + 8][kk * 8 + t4    ]);
            unsigned a2 = __float_as_uint(As[wr + g    ][kk * 8 + t4 + 4]);
            unsigned a3 = __float_as_uint(As[wr + g + 8][kk * 8 + t4 + 4]);
            #pragma unroll
            for (int nt = 0; nt < 8; nt++) {
                unsigned b0 = __float_as_uint(Ws[kk * 8 + t4    ][nt * 8 + g]);
                unsigned b1 = __float_as_uint(Ws[kk * 8 + t4 + 4][nt * 8 + g]);
                asm volatile(
                    "mma.sync.aligned.m16n8k8.row.col.f32.tf32.tf32.f32 "
                    "{%0,%1,%2,%3}, {%4,%5,%6,%7}, {%8,%9}, {%0,%1,%2,%3};"
                    : "+f"(acc[nt][0]), "+f"(acc[nt][1]),
                      "+f"(acc[nt][2]), "+f"(acc[nt][3])
                    : "r"(a0), "r"(a1), "r"(a2), "r"(a3), "r"(b0), "r"(b1));
            }
        }
        __syncthreads();
    }

    // epilogue (+ optional fused attention logits)
    int wr = warp * 16;
    float el0 = 0.f, er0 = 0.f, el1 = 0.f, er1 = 0.f;
    int head = blockIdx.y;
    #pragma unroll
    for (int nt = 0; nt < 8; nt++) {
        int col = c0 + nt * 8 + t4 * 2;
        float bx = 0.f, by = 0.f;
        if (bias) { bx = bias[col]; by = bias[col + 1]; }
        float v0 = acc[nt][0] + bx, v1 = acc[nt][1] + by;
        float v2 = acc[nt][2] + bx, v3 = acc[nt][3] + by;
        if (relu) {
            v0 = fmaxf(v0, 0.f); v1 = fmaxf(v1, 0.f);
            v2 = fmaxf(v2, 0.f); v3 = fmaxf(v3, 0.f);
        }
        if (ATTN) {
            int lc = head * 64 + nt * 8 + t4 * 2;
            float a0 = al[lc], a1 = al[lc + 1];
            float q0 = ar[lc], q1 = ar[lc + 1];
            el0 = fmaf(v0, a0, fmaf(v1, a1, el0));
            er0 = fmaf(v0, q0, fmaf(v1, q1, er0));
            el1 = fmaf(v2, a0, fmaf(v3, a1, el1));
            er1 = fmaf(v2, q0, fmaf(v3, q1, er1));
        }
        int row0 = r0 + wr + g, row1 = row0 + 8;
        if (row0 < n) *(float2*)&C[(size_t)row0 * M + col] = make_float2(v0, v1);
        if (row1 < n) *(float2*)&C[(size_t)row1 * M + col] = make_float2(v2, v3);
    }
    if (ATTN) {
        #pragma unroll
        for (int o = 1; o <= 2; o <<= 1) {
            el0 += __shfl_xor_sync(0xffffffffu, el0, o);
            er0 += __shfl_xor_sync(0xffffffffu, er0, o);
            el1 += __shfl_xor_sync(0xffffffffu, el1, o);
            er1 += __shfl_xor_sync(0xffffffffu, er1, o);
        }
        if (t4 == 0) {
            int row0 = r0 + wr + g, row1 = row0 + 8;
            if (row0 < n) { g_el[row0 * 2 + head] = el0; g_er[row0 * 2 + head] = er0; }
            if (row1 < n) { g_el[row1 * 2 + head] = el1; g_er[row1 * 2 + head] = er1; }
        }
    }
}

// ======================= CSR build (3-stage scan — proven, no spin-waits) =====
__global__ void k_zero() {
    int i = blockIdx.x * blockDim.x + threadIdx.x;
    if (i < NN) g_cnt[i] = 0;
}
__global__ void k_hist(const int* __restrict__ dst) {
    int e = blockIdx.x * blockDim.x + threadIdx.x;
    if (e < EE) atomicAdd(&g_cnt[dst[e]], 1);
}
__global__ void k_scan1() {   // 98 blocks x 512
    __shared__ int s[512];
    int i = blockIdx.x * 512 + threadIdx.x;
    int v = (i < NN) ? g_cnt[i] : 0;
    s[threadIdx.x] = v;
    __syncthreads();
    for (int off = 1; off < 512; off <<= 1) {
        int t = (threadIdx.x >= off) ? s[threadIdx.x - off] : 0;
        __syncthreads();
        s[threadIdx.x] += t;
        __syncthreads();
    }
    if (i < NN) g_tmp[i] = s[threadIdx.x];
    if (threadIdx.x == 511) g_bsum[blockIdx.x] = s[511];
}
__global__ void k_scan2() {   // 1 block x 128 scans the 98 block sums
    __shared__ int s[128];
    int v = (threadIdx.x < 98) ? g_bsum[threadIdx.x] : 0;
    s[threadIdx.x] = v;
    __syncthreads();
    for (int off = 1; off < 128; off <<= 1) {
        int t = (threadIdx.x >= off) ? s[threadIdx.x - off] : 0;
        __syncthreads();
        s[threadIdx.x] += t;
        __syncthreads();
    }
    if (threadIdx.x < 98) g_bsum[threadIdx.x] = s[threadIdx.x] - v;  // exclusive
}
__global__ void k_scan3() {
    int i = blockIdx.x * blockDim.x + threadIdx.x;
    if (i >= NN) return;
    int off = g_bsum[i >> 9];
    int excl = g_tmp[i] - g_cnt[i] + off;
    g_rowptr[i] = excl;
    g_wptr[i]   = excl;
    if (i == NN - 1) g_rowptr[NN] = g_tmp[i] + off;
}
__global__ void k_scatter(const int* __restrict__ src, const int* __restrict__ dst) {
    int e = blockIdx.x * blockDim.x + threadIdx.x;
    if (e >= EE) return;
    int p = atomicAdd(&g_wptr[dst[e]], 1);
    g_srcs[p] = src[e];
}

// ======================= fused edge-softmax + aggregation =======================
__global__ void __launch_bounds__(256)
gat_agg(const float* __restrict__ bias, float* __restrict__ outp) {
    __shared__ float2 s_ex[8][32];
    __shared__ int    s_src[8][32];
    int lane = threadIdx.x & 31, w = threadIdx.x >> 5;
    int d = blockIdx.x * 8 + w;
    if (d >= NN) return;
    int beg = g_rowptr[d], end = g_rowptr[d + 1];
    float2 er2 = *(const float2*)(g_er + 2 * d);
    const float4* feat4 = (const float4*)g_feat;

    float4 acc = make_float4(0.f, 0.f, 0.f, 0.f);
    float z0 = 0.f, z1 = 0.f;

    for (int c = beg; c < end; c += 32) {
        int idx = c + lane;
        bool valid = idx < end;
        int s = valid ? g_srcs[idx] : 0;
        float2 el2 = *(const float2*)(g_el + 2 * s);
        float e0 = el2.x + er2.x; e0 = e0 > 0.f ? e0 : 0.2f * e0;
        float e1 = el2.y + er2.y; e1 = e1 > 0.f ? e1 : 0.2f * e1;
        float x0 = valid ? __expf(e0) : 0.f;
        float x1 = valid ? __expf(e1) : 0.f;
        z0 += x0; z1 += x1;
        s_ex[w][lane]  = make_float2(x0, x1);
        s_src[w][lane] = s;
        __syncwarp();
        int m = min(32, end - c);
        #pragma unroll 4
        for (int j = 0; j < m; j++) {
            int sj = s_src[w][j];
            float2 exj = s_ex[w][j];
            float wgt = (lane < 16) ? exj.x : exj.y;
            float4 f = feat4[(size_t)sj * 32 + lane];
            acc.x = fmaf(wgt, f.x, acc.x);
            acc.y = fmaf(wgt, f.y, acc.y);
            acc.z = fmaf(wgt, f.z, acc.z);
            acc.w = fmaf(wgt, f.w, acc.w);
        }
        __syncwarp();
    }
    #pragma unroll
    for (int o = 16; o > 0; o >>= 1) {
        z0 += __shfl_xor_sync(0xffffffffu, z0, o);
        z1 += __shfl_xor_sync(0xffffffffu, z1, o);
    }
    float z = (lane < 16) ? z0 : z1;
    float ia = (z > 0.f) ? __fdividef(1.f, z) : 0.f;
    float4 b4 = ((const float4*)bias)[lane];
    float4 o4;
    o4.x = fmaf(acc.x, ia, b4.x);
    o4.y = fmaf(acc.y, ia, b4.y);
    o4.z = fmaf(acc.z, ia, b4.z);
    o4.w = fmaf(acc.w, ia, b4.w);
    ((float4*)outp)[(size_t)d * 32 + lane] = o4;
}

// ======================= host =======================
extern "C" void kernel_launch(void* const* d_in, const int* in_sizes, int n_in,
                              void* d_out, int out_size) {
    const float* h     = (const float*)d_in[0];
    const int*   src   = (const int*)d_in[1];
    const int*   dst   = (const int*)d_in[2];
    const float* W1    = (const float*)d_in[3];
    const float* al1   = (const float*)d_in[4];
    const float* ar1   = (const float*)d_in[5];
    const float* b1    = (const float*)d_in[6];
    const float* lin1W = (const float*)d_in[7];
    const float* lin1b = (const float*)d_in[8];
    const float* W2    = (const float*)d_in[9];
    const float* al2   = (const float*)d_in[10];
    const float* ar2   = (const float*)d_in[11];
    const float* b2    = (const float*)d_in[12];
    const float* lin2W = (const float*)d_in[13];
    const float* lin2b = (const float*)d_in[14];
    float* out = (float*)d_out;

    float *feat, *agg, *x;
    cudaGetSymbolAddress((void**)&feat, g_feat);
    cudaGetSymbolAddress((void**)&agg,  g_agg);
    cudaGetSymbolAddress((void**)&x,    g_x);

    const int ROWT  = (NN + 127) / 128;           // 391
    const int NB    = (NN + 255) / 256;           // 196
    const int EB    = (EE + 255) / 256;           // 3125
    const int WARPB = (NN * 32 + 255) / 256;      // 6250

    // ---- CSR build ----
    k_zero<<<NB, 256>>>();
    k_hist<<<EB, 256>>>(dst);
    k_scan1<<<98, 512>>>();
    k_scan2<<<1, 128>>>();
    k_scan3<<<NB, 256>>>();
    k_scatter<<<EB, 256>>>(src, dst);

    // ---- layer 1 ----
    gemm_mma<128, 128, true ><<<dim3(ROWT, 2), 256>>>(h, W1, nullptr, feat, NN, 0, al1, ar1);
    gat_agg<<<WARPB, 256>>>(b1, agg);
    gemm_mma<128, 64, false><<<dim3(ROWT, 1), 256>>>(agg, lin1W, lin1b, x, NN, 1, nullptr, nullptr);

    // ---- layer 2 ----
    gemm_mma<64, 128, true ><<<dim3(ROWT, 2), 256>>>(x, W2, nullptr, feat, NN, 0, al2, ar2);
    gat_agg<<<WARPB, 256>>>(b2, agg);
    gemm_mma<128, 64, false><<<dim3(ROWT, 1), 256>>>(agg, lin2W, lin2b, out, NN, 0, nullptr, nullptr);
}

// round 8
// speedup vs baseline: 2.4900x; 1.0516x over previous
#include <cuda_runtime.h>
#include <cuda_fp16.h>
#include <cuda_bf16.h>

#define NN 50000
#define EE 800000

// ---------------- scratch (no allocations allowed) ----------------
__device__ __half2 g_feat_h[NN * 64];   // per-layer fc output, fp16 [N, H*D]
__device__ float g_agg [NN * 128];
__device__ float g_x   [NN * 64];
__device__ float g_el  [NN * 2];
__device__ float g_er  [NN * 2];
// CSR scratch (g_cnt is zero at load; k_scan3 re-zeros it after use)
__device__ int g_cnt[NN];
__device__ int g_tmp[NN];
__device__ int g_rowptr[NN + 1];
__device__ int g_wptr[NN];
__device__ int g_srcs[EE];
__device__ int g_bsum[128];

// ---------------- helpers ----------------
__device__ __forceinline__ unsigned f2tf(float x) {
    unsigned u;
    asm("cvt.rna.tf32.f32 %0, %1;" : "=r"(u) : "f"(x));
    return u;
}

// ======================= tf32 tensor-core GEMM (+ fused attn logits) ==========
// C[n,M] = A[n,K] @ W[K,M] (+bias,+relu). 128x64 tile, 256 thr, m16n8k8 mma.
// If ATTN: M==128, blockIdx.y == head; epilogue writes fp16 feat + g_el/g_er
// (and does NOT write fp32 C). Otherwise writes fp32 C.
template<int K, int M, bool ATTN>
__global__ void __launch_bounds__(256)
gemm_mma(const float* __restrict__ A, const float* __restrict__ W,
         const float* __restrict__ bias, float* __restrict__ C,
         int n, int relu, const float* __restrict__ al, const float* __restrict__ ar) {
    __shared__ float As[128][36];
    __shared__ float Ws[32][72];
    int tid  = threadIdx.x;
    int lane = tid & 31, warp = tid >> 5;
    int g = lane >> 2, t4 = lane & 3;
    int r0 = blockIdx.x * 128;
    int c0 = blockIdx.y * 64;

    float acc[8][4];
    #pragma unroll
    for (int i = 0; i < 8; i++)
        #pragma unroll
        for (int j = 0; j < 4; j++) acc[i][j] = 0.f;

    // register prefetch buffers
    float4 va[4], vw[2];

    // preload kc = 0
    #pragma unroll
    for (int it = 0; it < 4; it++) {
        int f4 = tid + it * 256;
        int row = f4 >> 3, kq = (f4 & 7) * 4;
        va[it] = make_float4(0.f, 0.f, 0.f, 0.f);
        if (r0 + row < n) va[it] = *(const float4*)&A[(size_t)(r0 + row) * K + kq];
    }
    #pragma unroll
    for (int it = 0; it < 2; it++) {
        int f4 = tid + it * 256;
        int k = f4 >> 4, cq = (f4 & 15) * 4;
        vw[it] = *(const float4*)&W[(size_t)k * M + c0 + cq];
    }

    for (int kc = 0; kc < K; kc += 32) {
        // commit prefetched tile to smem (tf32-rounded)
        #pragma unroll
        for (int it = 0; it < 4; it++) {
            int f4 = tid + it * 256;
            int row = f4 >> 3, kq = (f4 & 7) * 4;
            As[row][kq + 0] = __uint_as_float(f2tf(va[it].x));
            As[row][kq + 1] = __uint_as_float(f2tf(va[it].y));
            As[row][kq + 2] = __uint_as_float(f2tf(va[it].z));
            As[row][kq + 3] = __uint_as_float(f2tf(va[it].w));
        }
        #pragma unroll
        for (int it = 0; it < 2; it++) {
            int f4 = tid + it * 256;
            int k = f4 >> 4, cq = (f4 & 15) * 4;
            Ws[k][cq + 0] = __uint_as_float(f2tf(vw[it].x));
            Ws[k][cq + 1] = __uint_as_float(f2tf(vw[it].y));
            Ws[k][cq + 2] = __uint_as_float(f2tf(vw[it].z));
            Ws[k][cq + 3] = __uint_as_float(f2tf(vw[it].w));
        }
        __syncthreads();

        // prefetch next slab (overlaps with MMA below)
        if (kc + 32 < K) {
            #pragma unroll
            for (int it = 0; it < 4; it++) {
                int f4 = tid + it * 256;
                int row = f4 >> 3, kq = (f4 & 7) * 4;
                va[it] = make_float4(0.f, 0.f, 0.f, 0.f);
                if (r0 + row < n)
                    va[it] = *(const float4*)&A[(size_t)(r0 + row) * K + kc + 32 + kq];
            }
            #pragma unroll
            for (int it = 0; it < 2; it++) {
                int f4 = tid + it * 256;
                int k = f4 >> 4, cq = (f4 & 15) * 4;
                vw[it] = *(const float4*)&W[(size_t)(kc + 32 + k) * M + c0 + cq];
            }
        }

        int wr = warp * 16;
        #pragma unroll
        for (int kk = 0; kk < 4; kk++) {
            unsigned a0 = __float_as_uint(As[wr + g    ][kk * 8 + t4    ]);
            unsigned a1 = __float_as_uint(As[wr + g + 8][kk * 8 + t4    ]);
            unsigned a2 = __float_as_uint(As[wr + g    ][kk * 8 + t4 + 4]);
            unsigned a3 = __float_as_uint(As[wr + g + 8][kk * 8 + t4 + 4]);
            #pragma unroll
            for (int nt = 0; nt < 8; nt++) {
                unsigned b0 = __float_as_uint(Ws[kk * 8 + t4    ][nt * 8 + g]);
                unsigned b1 = __float_as_uint(Ws[kk * 8 + t4 + 4][nt * 8 + g]);
                asm volatile(
                    "mma.sync.aligned.m16n8k8.row.col.f32.tf32.tf32.f32 "
                    "{%0,%1,%2,%3}, {%4,%5,%6,%7}, {%8,%9}, {%0,%1,%2,%3};"
                    : "+f"(acc[nt][0]), "+f"(acc[nt][1]),
                      "+f"(acc[nt][2]), "+f"(acc[nt][3])
                    : "r"(a0), "r"(a1), "r"(a2), "r"(a3), "r"(b0), "r"(b1));
            }
        }
        __syncthreads();
    }

    // epilogue (+ optional fused attention logits)
    int wr = warp * 16;
    float el0 = 0.f, er0 = 0.f, el1 = 0.f, er1 = 0.f;
    int head = blockIdx.y;
    #pragma unroll
    for (int nt = 0; nt < 8; nt++) {
        int col = c0 + nt * 8 + t4 * 2;
        float bx = 0.f, by = 0.f;
        if (bias) { bx = bias[col]; by = bias[col + 1]; }
        float v0 = acc[nt][0] + bx, v1 = acc[nt][1] + by;
        float v2 = acc[nt][2] + bx, v3 = acc[nt][3] + by;
        if (relu) {
            v0 = fmaxf(v0, 0.f); v1 = fmaxf(v1, 0.f);
            v2 = fmaxf(v2, 0.f); v3 = fmaxf(v3, 0.f);
        }
        int row0 = r0 + wr + g, row1 = row0 + 8;
        if (ATTN) {
            int lc = head * 64 + nt * 8 + t4 * 2;
            float a0 = al[lc], a1 = al[lc + 1];
            float q0 = ar[lc], q1 = ar[lc + 1];
            el0 = fmaf(v0, a0, fmaf(v1, a1, el0));
            er0 = fmaf(v0, q0, fmaf(v1, q1, er0));
            el1 = fmaf(v2, a0, fmaf(v3, a1, el1));
            er1 = fmaf(v2, q0, fmaf(v3, q1, er1));
            // fp16 feat store (half2 index: col/2 within 64-wide half2 row)
            int hc = head * 32 + nt * 4 + t4;
            if (row0 < n) g_feat_h[(size_t)row0 * 64 + hc] = __floats2half2_rn(v0, v1);
            if (row1 < n) g_feat_h[(size_t)row1 * 64 + hc] = __floats2half2_rn(v2, v3);
        } else {
            if (row0 < n) *(float2*)&C[(size_t)row0 * M + col] = make_float2(v0, v1);
            if (row1 < n) *(float2*)&C[(size_t)row1 * M + col] = make_float2(v2, v3);
        }
    }
    if (ATTN) {
        #pragma unroll
        for (int o = 1; o <= 2; o <<= 1) {
            el0 += __shfl_xor_sync(0xffffffffu, el0, o);
            er0 += __shfl_xor_sync(0xffffffffu, er0, o);
            el1 += __shfl_xor_sync(0xffffffffu, el1, o);
            er1 += __shfl_xor_sync(0xffffffffu, er1, o);
        }
        if (t4 == 0) {
            int row0 = r0 + wr + g, row1 = row0 + 8;
            if (row0 < n) { g_el[row0 * 2 + head] = el0; g_er[row0 * 2 + head] = er0; }
            if (row1 < n) { g_el[row1 * 2 + head] = el1; g_er[row1 * 2 + head] = er1; }
        }
    }
}

// ======================= CSR build (3-stage scan — proven, no spin-waits) =====
__global__ void k_hist(const int* __restrict__ dst) {
    int e = blockIdx.x * blockDim.x + threadIdx.x;
    if (e < EE) atomicAdd(&g_cnt[dst[e]], 1);
}
__global__ void k_scan1() {   // 98 blocks x 512
    __shared__ int s[512];
    int i = blockIdx.x * 512 + threadIdx.x;
    int v = (i < NN) ? g_cnt[i] : 0;
    s[threadIdx.x] = v;
    __syncthreads();
    for (int off = 1; off < 512; off <<= 1) {
        int t = (threadIdx.x >= off) ? s[threadIdx.x - off] : 0;
        __syncthreads();
        s[threadIdx.x] += t;
        __syncthreads();
    }
    if (i < NN) g_tmp[i] = s[threadIdx.x];
    if (threadIdx.x == 511) g_bsum[blockIdx.x] = s[511];
}
__global__ void k_scan2() {   // 1 block x 128 scans the 98 block sums
    __shared__ int s[128];
    int v = (threadIdx.x < 98) ? g_bsum[threadIdx.x] : 0;
    s[threadIdx.x] = v;
    __syncthreads();
    for (int off = 1; off < 128; off <<= 1) {
        int t = (threadIdx.x >= off) ? s[threadIdx.x - off] : 0;
        __syncthreads();
        s[threadIdx.x] += t;
        __syncthreads();
    }
    if (threadIdx.x < 98) g_bsum[threadIdx.x] = s[threadIdx.x] - v;  // exclusive
}
__global__ void k_scan3() {
    int i = blockIdx.x * blockDim.x + threadIdx.x;
    if (i >= NN) return;
    int off = g_bsum[i >> 9];
    int excl = g_tmp[i] - g_cnt[i] + off;
    g_rowptr[i] = excl;
    g_wptr[i]   = excl;
    g_cnt[i]    = 0;                 // restore invariant: g_cnt==0 at next call
    if (i == NN - 1) g_rowptr[NN] = g_tmp[i] + off;
}
__global__ void k_scatter(const int* __restrict__ src, const int* __restrict__ dst) {
    int e = blockIdx.x * blockDim.x + threadIdx.x;
    if (e >= EE) return;
    int p = atomicAdd(&g_wptr[dst[e]], 1);
    g_srcs[p] = src[e];
}

// ======================= fused edge-softmax + aggregation =======================
// one warp per dst node; fp16 feat gather (256 B/row = 32 uint2), fp32 accumulate.
__global__ void __launch_bounds__(256)
gat_agg(const float* __restrict__ bias, float* __restrict__ outp) {
    __shared__ float2 s_ex[8][32];
    __shared__ int    s_src[8][32];
    int lane = threadIdx.x & 31, w = threadIdx.x >> 5;
    int d = blockIdx.x * 8 + w;
    if (d >= NN) return;
    int beg = g_rowptr[d], end = g_rowptr[d + 1];
    float2 er2 = *(const float2*)(g_er + 2 * d);
    const uint2* feath = (const uint2*)g_feat_h;   // 8B = 4 halves per lane

    float4 acc = make_float4(0.f, 0.f, 0.f, 0.f);
    float z0 = 0.f, z1 = 0.f;

    for (int c = beg; c < end; c += 32) {
        int idx = c + lane;
        bool valid = idx < end;
        int s = valid ? g_srcs[idx] : 0;
        float2 el2 = *(const float2*)(g_el + 2 * s);
        float e0 = el2.x + er2.x; e0 = e0 > 0.f ? e0 : 0.2f * e0;
        float e1 = el2.y + er2.y; e1 = e1 > 0.f ? e1 : 0.2f * e1;
        float x0 = valid ? __expf(e0) : 0.f;
        float x1 = valid ? __expf(e1) : 0.f;
        z0 += x0; z1 += x1;
        s_ex[w][lane]  = make_float2(x0, x1);
        s_src[w][lane] = s;
        __syncwarp();
        int m = min(32, end - c);
        #pragma unroll 4
        for (int j = 0; j < m; j++) {
            int sj = s_src[w][j];
            float2 exj = s_ex[w][j];
            float wgt = (lane < 16) ? exj.x : exj.y;
            // row = 128 halves = 32 uint2; lane covers cols 4*lane..4*lane+3
            uint2 u = feath[(size_t)sj * 32 + lane];
            float2 fa = __half22float2(*(const __half2*)&u.x);
            float2 fb = __half22float2(*(const __half2*)&u.y);
            acc.x = fmaf(wgt, fa.x, acc.x);
            acc.y = fmaf(wgt, fa.y, acc.y);
            acc.z = fmaf(wgt, fb.x, acc.z);
            acc.w = fmaf(wgt, fb.y, acc.w);
        }
        __syncwarp();
    }
    #pragma unroll
    for (int o = 16; o > 0; o >>= 1) {
        z0 += __shfl_xor_sync(0xffffffffu, z0, o);
        z1 += __shfl_xor_sync(0xffffffffu, z1, o);
    }
    float z = (lane < 16) ? z0 : z1;
    float ia = (z > 0.f) ? __fdividef(1.f, z) : 0.f;
    float4 b4 = ((const float4*)bias)[lane];
    float4 o4;
    o4.x = fmaf(acc.x, ia, b4.x);
    o4.y = fmaf(acc.y, ia, b4.y);
    o4.z = fmaf(acc.z, ia, b4.z);
    o4.w = fmaf(acc.w, ia, b4.w);
    ((float4*)outp)[(size_t)d * 32 + lane] = o4;
}

// ======================= host =======================
extern "C" void kernel_launch(void* const* d_in, const int* in_sizes, int n_in,
                              void* d_out, int out_size) {
    const float* h     = (const float*)d_in[0];
    const int*   src   = (const int*)d_in[1];
    const int*   dst   = (const int*)d_in[2];
    const float* W1    = (const float*)d_in[3];
    const float* al1   = (const float*)d_in[4];
    const float* ar1   = (const float*)d_in[5];
    const float* b1    = (const float*)d_in[6];
    const float* lin1W = (const float*)d_in[7];
    const float* lin1b = (const float*)d_in[8];
    const float* W2    = (const float*)d_in[9];
    const float* al2   = (const float*)d_in[10];
    const float* ar2   = (const float*)d_in[11];
    const float* b2    = (const float*)d_in[12];
    const float* lin2W = (const float*)d_in[13];
    const float* lin2b = (const float*)d_in[14];
    float* out = (float*)d_out;

    float *agg, *x;
    cudaGetSymbolAddress((void**)&agg, g_agg);
    cudaGetSymbolAddress((void**)&x,   g_x);

    const int ROWT  = (NN + 127) / 128;           // 391
    const int NB    = (NN + 255) / 256;           // 196
    const int EB    = (EE + 255) / 256;           // 3125
    const int WARPB = (NN * 32 + 255) / 256;      // 6250

    // ---- CSR build (g_cnt is zero on entry; k_scan3 restores it) ----
    k_hist<<<EB, 256>>>(dst);
    k_scan1<<<98, 512>>>();
    k_scan2<<<1, 128>>>();
    k_scan3<<<NB, 256>>>();
    k_scatter<<<EB, 256>>>(src, dst);

    // ---- layer 1 ----
    gemm_mma<128, 128, true ><<<dim3(ROWT, 2), 256>>>(h, W1, nullptr, nullptr, NN, 0, al1, ar1);
    gat_agg<<<WARPB, 256>>>(b1, agg);
    gemm_mma<128, 64, false><<<dim3(ROWT, 1), 256>>>(agg, lin1W, lin1b, x, NN, 1, nullptr, nullptr);

    // ---- layer 2 ----
    gemm_mma<64, 128, true ><<<dim3(ROWT, 2), 256>>>(x, W2, nullptr, nullptr, NN, 0, al2, ar2);
    gat_agg<<<WARPB, 256>>>(b2, agg);
    gemm_mma<128, 64, false><<<dim3(ROWT, 1), 256>>>(agg, lin2W, lin2b, out, NN, 0, nullptr, nullptr);
}

// round 9
// speedup vs baseline: 2.5950x; 1.0421x over previous
#include <cuda_runtime.h>
#include <cuda_fp16.h>
#include <cuda_bf16.h>

#define NN 50000
#define EE 800000

// ---------------- scratch (no allocations allowed) ----------------
__device__ __half2 g_feat_h[NN * 64];   // per-layer fc output, fp16 [N, H*D]
__device__ float g_agg [NN * 128];
__device__ float g_x   [NN * 64];
__device__ float g_el  [NN * 2];
__device__ float g_er  [NN * 2];
// CSR scratch (g_cnt is zero at load; k_scan23 re-zeros it after use)
__device__ int g_cnt[NN];
__device__ int g_tmp[NN];
__device__ int g_rowptr[NN + 1];
__device__ int g_wptr[NN];
__device__ int g_srcs[EE];
__device__ int g_bsum[128];

// ---------------- helpers ----------------
__device__ __forceinline__ unsigned f2tf(float x) {
    unsigned u;
    asm("cvt.rna.tf32.f32 %0, %1;" : "=r"(u) : "f"(x));
    return u;
}
__device__ __forceinline__ void pdl_wait() {
    cudaGridDependencySynchronize();
}

// ======================= tf32 tensor-core GEMM (+ fused attn logits) ==========
// C[n,M] = A[n,K] @ W[K,M] (+bias,+relu). 128x64 tile, 256 thr, m16n8k8 mma.
// If ATTN: M==128, blockIdx.y == head; epilogue writes fp16 feat + g_el/g_er.
template<int K, int M, bool ATTN>
__global__ void __launch_bounds__(256)
gemm_mma(const float* __restrict__ A, const float* __restrict__ W,
         const float* __restrict__ bias, float* __restrict__ C,
         int n, int relu, const float* __restrict__ al, const float* __restrict__ ar) {
    pdl_wait();
    __shared__ float As[128][36];
    __shared__ float Ws[32][72];
    int tid  = threadIdx.x;
    int lane = tid & 31, warp = tid >> 5;
    int g = lane >> 2, t4 = lane & 3;
    int r0 = blockIdx.x * 128;
    int c0 = blockIdx.y * 64;

    float acc[8][4];
    #pragma unroll
    for (int i = 0; i < 8; i++)
        #pragma unroll
        for (int j = 0; j < 4; j++) acc[i][j] = 0.f;

    float4 va[4], vw[2];

    #pragma unroll
    for (int it = 0; it < 4; it++) {
        int f4 = tid + it * 256;
        int row = f4 >> 3, kq = (f4 & 7) * 4;
        va[it] = make_float4(0.f, 0.f, 0.f, 0.f);
        if (r0 + row < n) va[it] = *(const float4*)&A[(size_t)(r0 + row) * K + kq];
    }
    #pragma unroll
    for (int it = 0; it < 2; it++) {
        int f4 = tid + it * 256;
        int k = f4 >> 4, cq = (f4 & 15) * 4;
        vw[it] = *(const float4*)&W[(size_t)k * M + c0 + cq];
    }

    for (int kc = 0; kc < K; kc += 32) {
        #pragma unroll
        for (int it = 0; it < 4; it++) {
            int f4 = tid + it * 256;
            int row = f4 >> 3, kq = (f4 & 7) * 4;
            As[row][kq + 0] = __uint_as_float(f2tf(va[it].x));
            As[row][kq + 1] = __uint_as_float(f2tf(va[it].y));
            As[row][kq + 2] = __uint_as_float(f2tf(va[it].z));
            As[row][kq + 3] = __uint_as_float(f2tf(va[it].w));
        }
        #pragma unroll
        for (int it = 0; it < 2; it++) {
            int f4 = tid + it * 256;
            int k = f4 >> 4, cq = (f4 & 15) * 4;
            Ws[k][cq + 0] = __uint_as_float(f2tf(vw[it].x));
            Ws[k][cq + 1] = __uint_as_float(f2tf(vw[it].y));
            Ws[k][cq + 2] = __uint_as_float(f2tf(vw[it].z));
            Ws[k][cq + 3] = __uint_as_float(f2tf(vw[it].w));
        }
        __syncthreads();

        if (kc + 32 < K) {
            #pragma unroll
            for (int it = 0; it < 4; it++) {
                int f4 = tid + it * 256;
                int row = f4 >> 3, kq = (f4 & 7) * 4;
                va[it] = make_float4(0.f, 0.f, 0.f, 0.f);
                if (r0 + row < n)
                    va[it] = *(const float4*)&A[(size_t)(r0 + row) * K + kc + 32 + kq];
            }
            #pragma unroll
            for (int it = 0; it < 2; it++) {
                int f4 = tid + it * 256;
                int k = f4 >> 4, cq = (f4 & 15) * 4;
                vw[it] = *(const float4*)&W[(size_t)(kc + 32 + k) * M + c0 + cq];
            }
        }

        int wr = warp * 16;
        #pragma unroll
        for (int kk = 0; kk < 4; kk++) {
            unsigned a0 = __float_as_uint(As[wr + g    ][kk * 8 + t4    ]);
            unsigned a1 = __float_as_uint(As[wr + g + 8][kk * 8 + t4    ]);
            unsigned a2 = __float_as_uint(As[wr + g    ][kk * 8 + t4 + 4]);
            unsigned a3 = __float_as_uint(As[wr + g + 8][kk * 8 + t4 + 4]);
            #pragma unroll
            for (int nt = 0; nt < 8; nt++) {
                unsigned b0 = __float_as_uint(Ws[kk * 8 + t4    ][nt * 8 + g]);
                unsigned b1 = __float_as_uint(Ws[kk * 8 + t4 + 4][nt * 8 + g]);
                asm volatile(
                    "mma.sync.aligned.m16n8k8.row.col.f32.tf32.tf32.f32 "
                    "{%0,%1,%2,%3}, {%4,%5,%6,%7}, {%8,%9}, {%0,%1,%2,%3};"
                    : "+f"(acc[nt][0]), "+f"(acc[nt][1]),
                      "+f"(acc[nt][2]), "+f"(acc[nt][3])
                    : "r"(a0), "r"(a1), "r"(a2), "r"(a3), "r"(b0), "r"(b1));
            }
        }
        __syncthreads();
    }

    int wr = warp * 16;
    float el0 = 0.f, er0 = 0.f, el1 = 0.f, er1 = 0.f;
    int head = blockIdx.y;
    #pragma unroll
    for (int nt = 0; nt < 8; nt++) {
        int col = c0 + nt * 8 + t4 * 2;
        float bx = 0.f, by = 0.f;
        if (bias) { bx = bias[col]; by = bias[col + 1]; }
        float v0 = acc[nt][0] + bx, v1 = acc[nt][1] + by;
        float v2 = acc[nt][2] + bx, v3 = acc[nt][3] + by;
        if (relu) {
            v0 = fmaxf(v0, 0.f); v1 = fmaxf(v1, 0.f);
            v2 = fmaxf(v2, 0.f); v3 = fmaxf(v3, 0.f);
        }
        int row0 = r0 + wr + g, row1 = row0 + 8;
        if (ATTN) {
            int lc = head * 64 + nt * 8 + t4 * 2;
            float a0 = al[lc], a1 = al[lc + 1];
            float q0 = ar[lc], q1 = ar[lc + 1];
            el0 = fmaf(v0, a0, fmaf(v1, a1, el0));
            er0 = fmaf(v0, q0, fmaf(v1, q1, er0));
            el1 = fmaf(v2, a0, fmaf(v3, a1, el1));
            er1 = fmaf(v2, q0, fmaf(v3, q1, er1));
            int hc = head * 32 + nt * 4 + t4;
            if (row0 < n) g_feat_h[(size_t)row0 * 64 + hc] = __floats2half2_rn(v0, v1);
            if (row1 < n) g_feat_h[(size_t)row1 * 64 + hc] = __floats2half2_rn(v2, v3);
        } else {
            if (row0 < n) *(float2*)&C[(size_t)row0 * M + col] = make_float2(v0, v1);
            if (row1 < n) *(float2*)&C[(size_t)row1 * M + col] = make_float2(v2, v3);
        }
    }
    if (ATTN) {
        #pragma unroll
        for (int o = 1; o <= 2; o <<= 1) {
            el0 += __shfl_xor_sync(0xffffffffu, el0, o);
            er0 += __shfl_xor_sync(0xffffffffu, er0, o);
            el1 += __shfl_xor_sync(0xffffffffu, el1, o);
            er1 += __shfl_xor_sync(0xffffffffu, er1, o);
        }
        if (t4 == 0) {
            int row0 = r0 + wr + g, row1 = row0 + 8;
            if (row0 < n) { g_el[row0 * 2 + head] = el0; g_er[row0 * 2 + head] = er0; }
            if (row1 < n) { g_el[row1 * 2 + head] = el1; g_er[row1 * 2 + head] = er1; }
        }
    }
}

// ======================= CSR build =======================
__global__ void k_hist(const int* __restrict__ dst) {
    pdl_wait();
    int e = blockIdx.x * blockDim.x + threadIdx.x;
    if (e < EE) atomicAdd(&g_cnt[dst[e]], 1);
}
__global__ void k_scan1() {   // 98 blocks x 512: per-block inclusive scans
    pdl_wait();
    __shared__ int s[512];
    int i = blockIdx.x * 512 + threadIdx.x;
    int v = (i < NN) ? g_cnt[i] : 0;
    s[threadIdx.x] = v;
    __syncthreads();
    for (int off = 1; off < 512; off <<= 1) {
        int t = (threadIdx.x >= off) ? s[threadIdx.x - off] : 0;
        __syncthreads();
        s[threadIdx.x] += t;
        __syncthreads();
    }
    if (i < NN) g_tmp[i] = s[threadIdx.x];
    if (threadIdx.x == 511) g_bsum[blockIdx.x] = s[511];
}
// scan2+scan3 merged: every block redundantly scans the 98 block sums (cheap),
// then finalizes rowptr/wptr and restores g_cnt = 0.
__global__ void k_scan23() {
    pdl_wait();
    __shared__ int sb[128];
    int tid = threadIdx.x;
    if (tid < 128) sb[tid] = (tid < 98) ? g_bsum[tid] : 0;
    __syncthreads();
    for (int off = 1; off < 128; off <<= 1) {
        int t = (tid < 128 && tid >= off) ? sb[tid - off] : 0;
        __syncthreads();
        if (tid < 128) sb[tid] += t;
        __syncthreads();
    }
    int i = blockIdx.x * blockDim.x + tid;
    if (i >= NN) return;
    int j = i >> 9;
    int off = (j == 0) ? 0 : sb[j - 1];
    int excl = g_tmp[i] - g_cnt[i] + off;
    g_rowptr[i] = excl;
    g_wptr[i]   = excl;
    g_cnt[i]    = 0;                 // restore invariant: g_cnt==0 at next call
    if (i == NN - 1) g_rowptr[NN] = g_tmp[i] + off;
}
__global__ void k_scatter(const int* __restrict__ src, const int* __restrict__ dst) {
    pdl_wait();
    int e = blockIdx.x * blockDim.x + threadIdx.x;
    if (e >= EE) return;
    int p = atomicAdd(&g_wptr[dst[e]], 1);
    g_srcs[p] = src[e];
}

// ======================= fused edge-softmax + aggregation =======================
// one warp per dst node; fp16 feat gather (256 B/row = 32 uint2), fp32 accumulate.
__global__ void __launch_bounds__(256)
gat_agg(const float* __restrict__ bias, float* __restrict__ outp) {
    pdl_wait();
    __shared__ float2 s_ex[8][32];
    __shared__ int    s_src[8][32];
    int lane = threadIdx.x & 31, w = threadIdx.x >> 5;
    int d = blockIdx.x * 8 + w;
    if (d >= NN) return;
    int beg = g_rowptr[d], end = g_rowptr[d + 1];
    float2 er2 = *(const float2*)(g_er + 2 * d);
    const uint2* feath = (const uint2*)g_feat_h;

    float4 acc = make_float4(0.f, 0.f, 0.f, 0.f);
    float z0 = 0.f, z1 = 0.f;

    for (int c = beg; c < end; c += 32) {
        int idx = c + lane;
        bool valid = idx < end;
        int s = valid ? g_srcs[idx] : 0;
        float2 el2 = *(const float2*)(g_el + 2 * s);
        float e0 = el2.x + er2.x; e0 = e0 > 0.f ? e0 : 0.2f * e0;
        float e1 = el2.y + er2.y; e1 = e1 > 0.f ? e1 : 0.2f * e1;
        float x0 = valid ? __expf(e0) : 0.f;
        float x1 = valid ? __expf(e1) : 0.f;
        z0 += x0; z1 += x1;
        s_ex[w][lane]  = make_float2(x0, x1);
        s_src[w][lane] = s;
        __syncwarp();
        int m = min(32, end - c);
        #pragma unroll 4
        for (int j = 0; j < m; j++) {
            int sj = s_src[w][j];
            float2 exj = s_ex[w][j];
            float wgt = (lane < 16) ? exj.x : exj.y;
            uint2 u = feath[(size_t)sj * 32 + lane];
            float2 fa = __half22float2(*(const __half2*)&u.x);
            float2 fb = __half22float2(*(const __half2*)&u.y);
            acc.x = fmaf(wgt, fa.x, acc.x);
            acc.y = fmaf(wgt, fa.y, acc.y);
            acc.z = fmaf(wgt, fb.x, acc.z);
            acc.w = fmaf(wgt, fb.y, acc.w);
        }
        __syncwarp();
    }
    #pragma unroll
    for (int o = 16; o > 0; o >>= 1) {
        z0 += __shfl_xor_sync(0xffffffffu, z0, o);
        z1 += __shfl_xor_sync(0xffffffffu, z1, o);
    }
    float z = (lane < 16) ? z0 : z1;
    float ia = (z > 0.f) ? __fdividef(1.f, z) : 0.f;
    float4 b4 = ((const float4*)bias)[lane];
    float4 o4;
    o4.x = fmaf(acc.x, ia, b4.x);
    o4.y = fmaf(acc.y, ia, b4.y);
    o4.z = fmaf(acc.z, ia, b4.z);
    o4.w = fmaf(acc.w, ia, b4.w);
    ((float4*)outp)[(size_t)d * 32 + lane] = o4;
}

// ======================= host =======================
template<typename... Args>
static inline void pdl_launch(dim3 gd, dim3 bd, void (*kfn)(Args...), Args... args) {
    cudaLaunchConfig_t cfg = {};
    cfg.gridDim = gd;
    cfg.blockDim = bd;
    cudaLaunchAttribute at[1];
    at[0].id = cudaLaunchAttributeProgrammaticStreamSerialization;
    at[0].val.programmaticStreamSerializationAllowed = 1;
    cfg.attrs = at;
    cfg.numAttrs = 1;
    cudaLaunchKernelEx(&cfg, kfn, args...);
}

extern "C" void kernel_launch(void* const* d_in, const int* in_sizes, int n_in,
                              void* d_out, int out_size) {
    const float* h     = (const float*)d_in[0];
    const int*   src   = (const int*)d_in[1];
    const int*   dst   = (const int*)d_in[2];
    const float* W1    = (const float*)d_in[3];
    const float* al1   = (const float*)d_in[4];
    const float* ar1   = (const float*)d_in[5];
    const float* b1    = (const float*)d_in[6];
    const float* lin1W = (const float*)d_in[7];
    const float* lin1b = (const float*)d_in[8];
    const float* W2    = (const float*)d_in[9];
    const float* al2   = (const float*)d_in[10];
    const float* ar2   = (const float*)d_in[11];
    const float* b2    = (const float*)d_in[12];
    const float* lin2W = (const float*)d_in[13];
    const float* lin2b = (const float*)d_in[14];
    float* out = (float*)d_out;

    float *agg, *x;
    cudaGetSymbolAddress((void**)&agg, g_agg);
    cudaGetSymbolAddress((void**)&x,   g_x);

    const int ROWT  = (NN + 127) / 128;           // 391
    const int NB    = (NN + 255) / 256;           // 196
    const int EB    = (EE + 255) / 256;           // 3125
    const int WARPB = (NN * 32 + 255) / 256;      // 6250

    const float* nfc = nullptr;
    float*       nf  = nullptr;

    // ---- CSR build (g_cnt is zero on entry; k_scan23 restores it) ----
    pdl_launch(dim3(EB), dim3(256), k_hist, dst);
    pdl_launch(dim3(98), dim3(512), k_scan1);
    pdl_launch(dim3(NB), dim3(256), k_scan23);
    pdl_launch(dim3(EB), dim3(256), k_scatter, src, dst);

    // ---- layer 1 ----
    pdl_launch(dim3(ROWT, 2), dim3(256), gemm_mma<128, 128, true>,
               h, W1, nfc, nf, (int)NN, 0, al1, ar1);
    pdl_launch(dim3(WARPB), dim3(256), gat_agg, b1, agg);
    pdl_launch(dim3(ROWT, 1), dim3(256), gemm_mma<128, 64, false>,
               (const float*)agg, lin1W, lin1b, x, (int)NN, 1, nfc, nfc);

    // ---- layer 2 ----
    pdl_launch(dim3(ROWT, 2), dim3(256), gemm_mma<64, 128, true>,
               (const float*)x, W2, nfc, nf, (int)NN, 0, al2, ar2);
    pdl_launch(dim3(WARPB), dim3(256), gat_agg, b2, agg);
    pdl_launch(dim3(ROWT, 1), dim3(256), gemm_mma<128, 64, false>,
               (const float*)agg, lin2W, lin2b, out, (int)NN, 0, nfc, nfc);
}

// round 10
// speedup vs baseline: 2.7288x; 1.0516x over previous
#include <cuda_runtime.h>
#include <cuda_fp16.h>
#include <cuda_bf16.h>

#define NN 50000
#define EE 800000

// ---------------- scratch (no allocations allowed) ----------------
__device__ __half2 g_feat_h[NN * 64];   // per-layer fc output, fp16 [N, H*D]
__device__ float g_agg [NN * 128];
__device__ float g_x   [NN * 64];
__device__ float g_el  [NN * 2];
__device__ float g_er  [NN * 2];
// CSR scratch (g_cnt is zero at load; k_scan23 re-zeros it after use)
__device__ int g_cnt[NN];
__device__ int g_tmp[NN];
__device__ int g_rowptr[NN + 1];
__device__ int g_rank[EE];           // within-bucket rank per edge (from k_hist)
__device__ int g_srcs[EE];
__device__ int g_bsum[128];

// ---------------- helpers ----------------
__device__ __forceinline__ unsigned f2tf(float x) {
    unsigned u;
    asm("cvt.rna.tf32.f32 %0, %1;" : "=r"(u) : "f"(x));
    return u;
}
__device__ __forceinline__ void pdl_wait() {
    cudaGridDependencySynchronize();
}

// ======================= tf32 tensor-core GEMM (+ fused attn logits) ==========
// C[n,M] = A[n,K] @ W[K,M] (+bias,+relu). 128x64 tile, 256 thr, m16n8k8 mma.
// If ATTN: M==128, blockIdx.y == head; epilogue writes fp16 feat + g_el/g_er.
// If TRIG: fire programmatic-launch trigger early (next kernel is independent).
template<int K, int M, bool ATTN, bool TRIG>
__global__ void __launch_bounds__(256)
gemm_mma(const float* __restrict__ A, const float* __restrict__ W,
         const float* __restrict__ bias, float* __restrict__ C,
         int n, int relu, const float* __restrict__ al, const float* __restrict__ ar) {
    pdl_wait();
    if (TRIG) cudaTriggerProgrammaticLaunchCompletion();
    __shared__ float As[128][36];
    __shared__ float Ws[32][72];
    int tid  = threadIdx.x;
    int lane = tid & 31, warp = tid >> 5;
    int g = lane >> 2, t4 = lane & 3;
    int r0 = blockIdx.x * 128;
    int c0 = blockIdx.y * 64;

    float acc[8][4];
    #pragma unroll
    for (int i = 0; i < 8; i++)
        #pragma unroll
        for (int j = 0; j < 4; j++) acc[i][j] = 0.f;

    float4 va[4], vw[2];

    #pragma unroll
    for (int it = 0; it < 4; it++) {
        int f4 = tid + it * 256;
        int row = f4 >> 3, kq = (f4 & 7) * 4;
        va[it] = make_float4(0.f, 0.f, 0.f, 0.f);
        if (r0 + row < n) va[it] = *(const float4*)&A[(size_t)(r0 + row) * K + kq];
    }
    #pragma unroll
    for (int it = 0; it < 2; it++) {
        int f4 = tid + it * 256;
        int k = f4 >> 4, cq = (f4 & 15) * 4;
        vw[it] = *(const float4*)&W[(size_t)k * M + c0 + cq];
    }

    for (int kc = 0; kc < K; kc += 32) {
        #pragma unroll
        for (int it = 0; it < 4; it++) {
            int f4 = tid + it * 256;
            int row = f4 >> 3, kq = (f4 & 7) * 4;
            As[row][kq + 0] = __uint_as_float(f2tf(va[it].x));
            As[row][kq + 1] = __uint_as_float(f2tf(va[it].y));
            As[row][kq + 2] = __uint_as_float(f2tf(va[it].z));
            As[row][kq + 3] = __uint_as_float(f2tf(va[it].w));
        }
        #pragma unroll
        for (int it = 0; it < 2; it++) {
            int f4 = tid + it * 256;
            int k = f4 >> 4, cq = (f4 & 15) * 4;
            Ws[k][cq + 0] = __uint_as_float(f2tf(vw[it].x));
            Ws[k][cq + 1] = __uint_as_float(f2tf(vw[it].y));
            Ws[k][cq + 2] = __uint_as_float(f2tf(vw[it].z));
            Ws[k][cq + 3] = __uint_as_float(f2tf(vw[it].w));
        }
        __syncthreads();

        if (kc + 32 < K) {
            #pragma unroll
            for (int it = 0; it < 4; it++) {
                int f4 = tid + it * 256;
                int row = f4 >> 3, kq = (f4 & 7) * 4;
                va[it] = make_float4(0.f, 0.f, 0.f, 0.f);
                if (r0 + row < n)
                    va[it] = *(const float4*)&A[(size_t)(r0 + row) * K + kc + 32 + kq];
            }
            #pragma unroll
            for (int it = 0; it < 2; it++) {
                int f4 = tid + it * 256;
                int k = f4 >> 4, cq = (f4 & 15) * 4;
                vw[it] = *(const float4*)&W[(size_t)(kc + 32 + k) * M + c0 + cq];
            }
        }

        int wr = warp * 16;
        #pragma unroll
        for (int kk = 0; kk < 4; kk++) {
            unsigned a0 = __float_as_uint(As[wr + g    ][kk * 8 + t4    ]);
            unsigned a1 = __float_as_uint(As[wr + g + 8][kk * 8 + t4    ]);
            unsigned a2 = __float_as_uint(As[wr + g    ][kk * 8 + t4 + 4]);
            unsigned a3 = __float_as_uint(As[wr + g + 8][kk * 8 + t4 + 4]);
            #pragma unroll
            for (int nt = 0; nt < 8; nt++) {
                unsigned b0 = __float_as_uint(Ws[kk * 8 + t4    ][nt * 8 + g]);
                unsigned b1 = __float_as_uint(Ws[kk * 8 + t4 + 4][nt * 8 + g]);
                asm volatile(
                    "mma.sync.aligned.m16n8k8.row.col.f32.tf32.tf32.f32 "
                    "{%0,%1,%2,%3}, {%4,%5,%6,%7}, {%8,%9}, {%0,%1,%2,%3};"
                    : "+f"(acc[nt][0]), "+f"(acc[nt][1]),
                      "+f"(acc[nt][2]), "+f"(acc[nt][3])
                    : "r"(a0), "r"(a1), "r"(a2), "r"(a3), "r"(b0), "r"(b1));
            }
        }
        __syncthreads();
    }

    int wr = warp * 16;
    float el0 = 0.f, er0 = 0.f, el1 = 0.f, er1 = 0.f;
    int head = blockIdx.y;
    #pragma unroll
    for (int nt = 0; nt < 8; nt++) {
        int col = c0 + nt * 8 + t4 * 2;
        float bx = 0.f, by = 0.f;
        if (bias) { bx = bias[col]; by = bias[col + 1]; }
        float v0 = acc[nt][0] + bx, v1 = acc[nt][1] + by;
        float v2 = acc[nt][2] + bx, v3 = acc[nt][3] + by;
        if (relu) {
            v0 = fmaxf(v0, 0.f); v1 = fmaxf(v1, 0.f);
            v2 = fmaxf(v2, 0.f); v3 = fmaxf(v3, 0.f);
        }
        int row0 = r0 + wr + g, row1 = row0 + 8;
        if (ATTN) {
            int lc = head * 64 + nt * 8 + t4 * 2;
            float a0 = al[lc], a1 = al[lc + 1];
            float q0 = ar[lc], q1 = ar[lc + 1];
            el0 = fmaf(v0, a0, fmaf(v1, a1, el0));
            er0 = fmaf(v0, q0, fmaf(v1, q1, er0));
            el1 = fmaf(v2, a0, fmaf(v3, a1, el1));
            er1 = fmaf(v2, q0, fmaf(v3, q1, er1));
            int hc = head * 32 + nt * 4 + t4;
            if (row0 < n) g_feat_h[(size_t)row0 * 64 + hc] = __floats2half2_rn(v0, v1);
            if (row1 < n) g_feat_h[(size_t)row1 * 64 + hc] = __floats2half2_rn(v2, v3);
        } else {
            if (row0 < n) *(float2*)&C[(size_t)row0 * M + col] = make_float2(v0, v1);
            if (row1 < n) *(float2*)&C[(size_t)row1 * M + col] = make_float2(v2, v3);
        }
    }
    if (ATTN) {
        #pragma unroll
        for (int o = 1; o <= 2; o <<= 1) {
            el0 += __shfl_xor_sync(0xffffffffu, el0, o);
            er0 += __shfl_xor_sync(0xffffffffu, er0, o);
            el1 += __shfl_xor_sync(0xffffffffu, el1, o);
            er1 += __shfl_xor_sync(0xffffffffu, er1, o);
        }
        if (t4 == 0) {
            int row0 = r0 + wr + g, row1 = row0 + 8;
            if (row0 < n) { g_el[row0 * 2 + head] = el0; g_er[row0 * 2 + head] = er0; }
            if (row1 < n) { g_el[row1 * 2 + head] = el1; g_er[row1 * 2 + head] = er1; }
        }
    }
}

// ======================= CSR build =======================
// hist runs CONCURRENTLY with the layer-1 ATTN GEMM (no grid sync: it reads
// only the dst input and g_cnt, which the previous call's k_scan23 re-zeroed).
__global__ void k_hist(const int* __restrict__ dst) {
    int e = blockIdx.x * blockDim.x + threadIdx.x;
    if (e < EE) {
        int p = atomicAdd(&g_cnt[dst[e]], 1);
        g_rank[e] = p;                       // within-bucket rank
    }
}
__global__ void k_scan1() {   // 98 blocks x 512: per-block inclusive scans
    pdl_wait();
    __shared__ int s[512];
    int i = blockIdx.x * 512 + threadIdx.x;
    int v = (i < NN) ? g_cnt[i] : 0;
    s[threadIdx.x] = v;
    __syncthreads();
    for (int off = 1; off < 512; off <<= 1) {
        int t = (threadIdx.x >= off) ? s[threadIdx.x - off] : 0;
        __syncthreads();
        s[threadIdx.x] += t;
        __syncthreads();
    }
    if (i < NN) g_tmp[i] = s[threadIdx.x];
    if (threadIdx.x == 511) g_bsum[blockIdx.x] = s[511];
}
// scan2+scan3 merged: every block redundantly scans the 98 block sums (cheap),
// then finalizes rowptr and restores g_cnt = 0.
__global__ void k_scan23() {
    pdl_wait();
    __shared__ int sb[128];
    int tid = threadIdx.x;
    if (tid < 128) sb[tid] = (tid < 98) ? g_bsum[tid] : 0;
    __syncthreads();
    for (int off = 1; off < 128; off <<= 1) {
        int t = (tid < 128 && tid >= off) ? sb[tid - off] : 0;
        __syncthreads();
        if (tid < 128) sb[tid] += t;
        __syncthreads();
    }
    int i = blockIdx.x * blockDim.x + tid;
    if (i >= NN) return;
    int j = i >> 9;
    int off = (j == 0) ? 0 : sb[j - 1];
    int excl = g_tmp[i] - g_cnt[i] + off;
    g_rowptr[i] = excl;
    g_cnt[i]    = 0;                 // restore invariant: g_cnt==0 at next call
    if (i == NN - 1) g_rowptr[NN] = g_tmp[i] + off;
}
// atomic-free scatter: position = rowptr[dst] + rank (recorded by k_hist)
__global__ void k_scatter(const int* __restrict__ src, const int* __restrict__ dst) {
    pdl_wait();
    int e = blockIdx.x * blockDim.x + threadIdx.x;
    if (e >= EE) return;
    int d = dst[e];
    g_srcs[g_rowptr[d] + g_rank[e]] = src[e];
}

// ======================= fused edge-softmax + aggregation =======================
// one warp per dst node; fp16 feat gather (256 B/row = 32 uint2), fp32 accumulate.
__global__ void __launch_bounds__(256)
gat_agg(const float* __restrict__ bias, float* __restrict__ outp) {
    pdl_wait();
    __shared__ float2 s_ex[8][32];
    __shared__ int    s_src[8][32];
    int lane = threadIdx.x & 31, w = threadIdx.x >> 5;
    int d = blockIdx.x * 8 + w;
    if (d >= NN) return;
    int beg = g_rowptr[d], end = g_rowptr[d + 1];
    float2 er2 = *(const float2*)(g_er + 2 * d);
    const uint2* feath = (const uint2*)g_feat_h;

    float4 acc = make_float4(0.f, 0.f, 0.f, 0.f);
    float z0 = 0.f, z1 = 0.f;

    for (int c = beg; c < end; c += 32) {
        int idx = c + lane;
        bool valid = idx < end;
        int s = valid ? g_srcs[idx] : 0;
        float2 el2 = *(const float2*)(g_el + 2 * s);
        float e0 = el2.x + er2.x; e0 = e0 > 0.f ? e0 : 0.2f * e0;
        float e1 = el2.y + er2.y; e1 = e1 > 0.f ? e1 : 0.2f * e1;
        float x0 = valid ? __expf(e0) : 0.f;
        float x1 = valid ? __expf(e1) : 0.f;
        z0 += x0; z1 += x1;
        s_ex[w][lane]  = make_float2(x0, x1);
        s_src[w][lane] = s;
        __syncwarp();
        int m = min(32, end - c);
        #pragma unroll 4
        for (int j = 0; j < m; j++) {
            int sj = s_src[w][j];
            float2 exj = s_ex[w][j];
            float wgt = (lane < 16) ? exj.x : exj.y;
            uint2 u = feath[(size_t)sj * 32 + lane];
            float2 fa = __half22float2(*(const __half2*)&u.x);
            float2 fb = __half22float2(*(const __half2*)&u.y);
            acc.x = fmaf(wgt, fa.x, acc.x);
            acc.y = fmaf(wgt, fa.y, acc.y);
            acc.z = fmaf(wgt, fb.x, acc.z);
            acc.w = fmaf(wgt, fb.y, acc.w);
        }
        __syncwarp();
    }
    #pragma unroll
    for (int o = 16; o > 0; o >>= 1) {
        z0 += __shfl_xor_sync(0xffffffffu, z0, o);
        z1 += __shfl_xor_sync(0xffffffffu, z1, o);
    }
    float z = (lane < 16) ? z0 : z1;
    float ia = (z > 0.f) ? __fdividef(1.f, z) : 0.f;
    float4 b4 = ((const float4*)bias)[lane];
    float4 o4;
    o4.x = fmaf(acc.x, ia, b4.x);
    o4.y = fmaf(acc.y, ia, b4.y);
    o4.z = fmaf(acc.z, ia, b4.z);
    o4.w = fmaf(acc.w, ia, b4.w);
    ((float4*)outp)[(size_t)d * 32 + lane] = o4;
}

// ======================= host =======================
template<typename... Args>
static inline void pdl_launch(dim3 gd, dim3 bd, void (*kfn)(Args...), Args... args) {
    cudaLaunchConfig_t cfg = {};
    cfg.gridDim = gd;
    cfg.blockDim = bd;
    cudaLaunchAttribute at[1];
    at[0].id = cudaLaunchAttributeProgrammaticStreamSerialization;
    at[0].val.programmaticStreamSerializationAllowed = 1;
    cfg.attrs = at;
    cfg.numAttrs = 1;
    cudaLaunchKernelEx(&cfg, kfn, args...);
}

extern "C" void kernel_launch(void* const* d_in, const int* in_sizes, int n_in,
                              void* d_out, int out_size) {
    const float* h     = (const float*)d_in[0];
    const int*   src   = (const int*)d_in[1];
    const int*   dst   = (const int*)d_in[2];
    const float* W1    = (const float*)d_in[3];
    const float* al1   = (const float*)d_in[4];
    const float* ar1   = (const float*)d_in[5];
    const float* b1    = (const float*)d_in[6];
    const float* lin1W = (const float*)d_in[7];
    const float* lin1b = (const float*)d_in[8];
    const float* W2    = (const float*)d_in[9];
    const float* al2   = (const float*)d_in[10];
    const float* ar2   = (const float*)d_in[11];
    const float* b2    = (const float*)d_in[12];
    const float* lin2W = (const float*)d_in[13];
    const float* lin2b = (const float*)d_in[14];
    float* out = (float*)d_out;

    float *agg, *x;
    cudaGetSymbolAddress((void**)&agg, g_agg);
    cudaGetSymbolAddress((void**)&x,   g_x);

    const int ROWT  = (NN + 127) / 128;           // 391
    const int NB    = (NN + 255) / 256;           // 196
    const int EB    = (EE + 255) / 256;           // 3125
    const int WARPB = (NN * 32 + 255) / 256;      // 6250

    const float* nfc = nullptr;
    float*       nf  = nullptr;

    // ---- layer-1 feat GEMM first (TRIG=true: fires early so k_hist overlaps) ----
    pdl_launch(dim3(ROWT, 2), dim3(256), gemm_mma<128, 128, true, true>,
               h, W1, nfc, nf, (int)NN, 0, al1, ar1);

    // ---- CSR build (hist overlaps gemm1; rest is a dependent chain) ----
    pdl_launch(dim3(EB), dim3(256), k_hist, dst);
    pdl_launch(dim3(98), dim3(512), k_scan1);
    pdl_launch(dim3(NB), dim3(256), k_scan23);
    pdl_launch(dim3(EB), dim3(256), k_scatter, src, dst);

    // ---- layer 1 aggregation + lin ----
    pdl_launch(dim3(WARPB), dim3(256), gat_agg, b1, agg);
    pdl_launch(dim3(ROWT, 1), dim3(256), gemm_mma<128, 64, false, false>,
               (const float*)agg, lin1W, lin1b, x, (int)NN, 1, nfc, nfc);

    // ---- layer 2 ----
    pdl_launch(dim3(ROWT, 2), dim3(256), gemm_mma<64, 128, true, false>,
               (const float*)x, W2, nfc, nf, (int)NN, 0, al2, ar2);
    pdl_launch(dim3(WARPB), dim3(256), gat_agg, b2, agg);
    pdl_launch(dim3(ROWT, 1), dim3(256), gemm_mma<128, 64, false, false>,
               (const float*)agg, lin2W, lin2b, out, (int)NN, 0, nfc, nfc);
}

// round 11
// speedup vs baseline: 2.7989x; 1.0257x over previous
#include <cuda_runtime.h>
#include <cuda_fp16.h>
#include <cuda_bf16.h>

#define NN 50000
#define EE 800000

// ---------------- scratch (no allocations allowed) ----------------
__device__ __half2 g_feat_h[NN * 64];   // ATTN fc output, fp16 [N, 128]
__device__ __half2 g_agg_h [NN * 64];   // conv output (agg+bias), fp16 [N, 128]
__device__ __half2 g_x_h   [NN * 32];   // layer-1 lin+relu output, fp16 [N, 64]
__device__ float g_el  [NN * 2];
__device__ float g_er  [NN * 2];
// CSR scratch (g_cnt is zero at load; k_scan23 re-zeros it after use)
__device__ int g_cnt[NN];
__device__ int g_tmp[NN];
__device__ int g_rowptr[NN + 1];
__device__ int g_rank[EE];           // within-bucket rank per edge (from k_hist)
__device__ int g_srcs[EE];
__device__ int g_bsum[128];

// ---------------- helpers ----------------
__device__ __forceinline__ unsigned f2tf(float x) {
    unsigned u;
    asm("cvt.rna.tf32.f32 %0, %1;" : "=r"(u) : "f"(x));
    return u;
}
__device__ __forceinline__ void pdl_wait() {
    cudaGridDependencySynchronize();
}

// ======================= tf32 tensor-core GEMM (+ fused attn logits) ==========
// C[n,M] = A[n,K] @ W[K,M] (+bias,+relu). 128x64 tile, 256 thr, m16n8k8 mma.
// AHALF: A is fp16 (__half row-major). CHALF: C written as fp16.
// ATTN: M==128, blockIdx.y == head; epilogue writes fp16 feat + g_el/g_er.
// TRIG: fire programmatic-launch trigger early (next kernel is independent).
template<int K, int M, bool ATTN, bool TRIG, bool AHALF, bool CHALF>
__global__ void __launch_bounds__(256)
gemm_mma(const void* __restrict__ Av, const float* __restrict__ W,
         const float* __restrict__ bias, void* __restrict__ Cv,
         int n, int relu, const float* __restrict__ al, const float* __restrict__ ar) {
    pdl_wait();
    if (TRIG) cudaTriggerProgrammaticLaunchCompletion();
    __shared__ float As[128][36];
    __shared__ float Ws[32][72];
    const float* Af = (const float*)Av;
    const __half* Ah = (const __half*)Av;
    int tid  = threadIdx.x;
    int lane = tid & 31, warp = tid >> 5;
    int g = lane >> 2, t4 = lane & 3;
    int r0 = blockIdx.x * 128;
    int c0 = blockIdx.y * 64;

    float acc[8][4];
    #pragma unroll
    for (int i = 0; i < 8; i++)
        #pragma unroll
        for (int j = 0; j < 4; j++) acc[i][j] = 0.f;

    float4 va[4]; uint2 vah[4]; float4 vw[2];

    #pragma unroll
    for (int it = 0; it < 4; it++) {
        int f4 = tid + it * 256;
        int row = f4 >> 3, kq = (f4 & 7) * 4;
        if (AHALF) {
            vah[it] = make_uint2(0u, 0u);
            if (r0 + row < n) vah[it] = *(const uint2*)&Ah[(size_t)(r0 + row) * K + kq];
        } else {
            va[it] = make_float4(0.f, 0.f, 0.f, 0.f);
            if (r0 + row < n) va[it] = *(const float4*)&Af[(size_t)(r0 + row) * K + kq];
        }
    }
    #pragma unroll
    for (int it = 0; it < 2; it++) {
        int f4 = tid + it * 256;
        int k = f4 >> 4, cq = (f4 & 15) * 4;
        vw[it] = *(const float4*)&W[(size_t)k * M + c0 + cq];
    }

    for (int kc = 0; kc < K; kc += 32) {
        #pragma unroll
        for (int it = 0; it < 4; it++) {
            int f4 = tid + it * 256;
            int row = f4 >> 3, kq = (f4 & 7) * 4;
            if (AHALF) {
                float2 p0 = __half22float2(*(const __half2*)&vah[it].x);
                float2 p1 = __half22float2(*(const __half2*)&vah[it].y);
                As[row][kq + 0] = p0.x;   // half fits in tf32 exactly
                As[row][kq + 1] = p0.y;
                As[row][kq + 2] = p1.x;
                As[row][kq + 3] = p1.y;
            } else {
                As[row][kq + 0] = __uint_as_float(f2tf(va[it].x));
                As[row][kq + 1] = __uint_as_float(f2tf(va[it].y));
                As[row][kq + 2] = __uint_as_float(f2tf(va[it].z));
                As[row][kq + 3] = __uint_as_float(f2tf(va[it].w));
            }
        }
        #pragma unroll
        for (int it = 0; it < 2; it++) {
            int f4 = tid + it * 256;
            int k = f4 >> 4, cq = (f4 & 15) * 4;
            Ws[k][cq + 0] = __uint_as_float(f2tf(vw[it].x));
            Ws[k][cq + 1] = __uint_as_float(f2tf(vw[it].y));
            Ws[k][cq + 2] = __uint_as_float(f2tf(vw[it].z));
            Ws[k][cq + 3] = __uint_as_float(f2tf(vw[it].w));
        }
        __syncthreads();

        if (kc + 32 < K) {
            #pragma unroll
            for (int it = 0; it < 4; it++) {
                int f4 = tid + it * 256;
                int row = f4 >> 3, kq = (f4 & 7) * 4;
                if (AHALF) {
                    vah[it] = make_uint2(0u, 0u);
                    if (r0 + row < n)
                        vah[it] = *(const uint2*)&Ah[(size_t)(r0 + row) * K + kc + 32 + kq];
                } else {
                    va[it] = make_float4(0.f, 0.f, 0.f, 0.f);
                    if (r0 + row < n)
                        va[it] = *(const float4*)&Af[(size_t)(r0 + row) * K + kc + 32 + kq];
                }
            }
            #pragma unroll
            for (int it = 0; it < 2; it++) {
                int f4 = tid + it * 256;
                int k = f4 >> 4, cq = (f4 & 15) * 4;
                vw[it] = *(const float4*)&W[(size_t)(kc + 32 + k) * M + c0 + cq];
            }
        }

        int wr = warp * 16;
        #pragma unroll
        for (int kk = 0; kk < 4; kk++) {
            unsigned a0 = __float_as_uint(As[wr + g    ][kk * 8 + t4    ]);
            unsigned a1 = __float_as_uint(As[wr + g + 8][kk * 8 + t4    ]);
            unsigned a2 = __float_as_uint(As[wr + g    ][kk * 8 + t4 + 4]);
            unsigned a3 = __float_as_uint(As[wr + g + 8][kk * 8 + t4 + 4]);
            #pragma unroll
            for (int nt = 0; nt < 8; nt++) {
                unsigned b0 = __float_as_uint(Ws[kk * 8 + t4    ][nt * 8 + g]);
                unsigned b1 = __float_as_uint(Ws[kk * 8 + t4 + 4][nt * 8 + g]);
                asm volatile(
                    "mma.sync.aligned.m16n8k8.row.col.f32.tf32.tf32.f32 "
                    "{%0,%1,%2,%3}, {%4,%5,%6,%7}, {%8,%9}, {%0,%1,%2,%3};"
                    : "+f"(acc[nt][0]), "+f"(acc[nt][1]),
                      "+f"(acc[nt][2]), "+f"(acc[nt][3])
                    : "r"(a0), "r"(a1), "r"(a2), "r"(a3), "r"(b0), "r"(b1));
            }
        }
        __syncthreads();
    }

    int wr = warp * 16;
    float el0 = 0.f, er0 = 0.f, el1 = 0.f, er1 = 0.f;
    int head = blockIdx.y;
    #pragma unroll
    for (int nt = 0; nt < 8; nt++) {
        int col = c0 + nt * 8 + t4 * 2;
        float bx = 0.f, by = 0.f;
        if (bias) { bx = bias[col]; by = bias[col + 1]; }
        float v0 = acc[nt][0] + bx, v1 = acc[nt][1] + by;
        float v2 = acc[nt][2] + bx, v3 = acc[nt][3] + by;
        if (relu) {
            v0 = fmaxf(v0, 0.f); v1 = fmaxf(v1, 0.f);
            v2 = fmaxf(v2, 0.f); v3 = fmaxf(v3, 0.f);
        }
        int row0 = r0 + wr + g, row1 = row0 + 8;
        if (ATTN) {
            int lc = head * 64 + nt * 8 + t4 * 2;
            float a0 = al[lc], a1 = al[lc + 1];
            float q0 = ar[lc], q1 = ar[lc + 1];
            el0 = fmaf(v0, a0, fmaf(v1, a1, el0));
            er0 = fmaf(v0, q0, fmaf(v1, q1, er0));
            el1 = fmaf(v2, a0, fmaf(v3, a1, el1));
            er1 = fmaf(v2, q0, fmaf(v3, q1, er1));
            int hc = head * 32 + nt * 4 + t4;
            if (row0 < n) g_feat_h[(size_t)row0 * 64 + hc] = __floats2half2_rn(v0, v1);
            if (row1 < n) g_feat_h[(size_t)row1 * 64 + hc] = __floats2half2_rn(v2, v3);
        } else if (CHALF) {
            __half2* Ch = (__half2*)Cv;
            if (row0 < n) Ch[((size_t)row0 * M + col) >> 1] = __floats2half2_rn(v0, v1);
            if (row1 < n) Ch[((size_t)row1 * M + col) >> 1] = __floats2half2_rn(v2, v3);
        } else {
            float* Cf = (float*)Cv;
            if (row0 < n) *(float2*)&Cf[(size_t)row0 * M + col] = make_float2(v0, v1);
            if (row1 < n) *(float2*)&Cf[(size_t)row1 * M + col] = make_float2(v2, v3);
        }
    }
    if (ATTN) {
        #pragma unroll
        for (int o = 1; o <= 2; o <<= 1) {
            el0 += __shfl_xor_sync(0xffffffffu, el0, o);
            er0 += __shfl_xor_sync(0xffffffffu, er0, o);
            el1 += __shfl_xor_sync(0xffffffffu, el1, o);
            er1 += __shfl_xor_sync(0xffffffffu, er1, o);
        }
        if (t4 == 0) {
            int row0 = r0 + wr + g, row1 = row0 + 8;
            if (row0 < n) { g_el[row0 * 2 + head] = el0; g_er[row0 * 2 + head] = er0; }
            if (row1 < n) { g_el[row1 * 2 + head] = el1; g_er[row1 * 2 + head] = er1; }
        }
    }
}

// ======================= CSR build =======================
// hist runs CONCURRENTLY with the layer-1 ATTN GEMM (no grid sync: it reads
// only the dst input and g_cnt, which the previous call's k_scan23 re-zeroed).
__global__ void k_hist(const int* __restrict__ dst) {
    int e = blockIdx.x * blockDim.x + threadIdx.x;
    if (e < EE) {
        int p = atomicAdd(&g_cnt[dst[e]], 1);
        g_rank[e] = p;                       // within-bucket rank
    }
}
__global__ void k_scan1() {   // 98 blocks x 512: per-block inclusive scans
    pdl_wait();
    __shared__ int s[512];
    int i = blockIdx.x * 512 + threadIdx.x;
    int v = (i < NN) ? g_cnt[i] : 0;
    s[threadIdx.x] = v;
    __syncthreads();
    for (int off = 1; off < 512; off <<= 1) {
        int t = (threadIdx.x >= off) ? s[threadIdx.x - off] : 0;
        __syncthreads();
        s[threadIdx.x] += t;
        __syncthreads();
    }
    if (i < NN) g_tmp[i] = s[threadIdx.x];
    if (threadIdx.x == 511) g_bsum[blockIdx.x] = s[511];
}
// scan2+scan3 merged: every block redundantly scans the 98 block sums (cheap),
// then finalizes rowptr and restores g_cnt = 0.
__global__ void k_scan23() {
    pdl_wait();
    __shared__ int sb[128];
    int tid = threadIdx.x;
    if (tid < 128) sb[tid] = (tid < 98) ? g_bsum[tid] : 0;
    __syncthreads();
    for (int off = 1; off < 128; off <<= 1) {
        int t = (tid < 128 && tid >= off) ? sb[tid - off] : 0;
        __syncthreads();
        if (tid < 128) sb[tid] += t;
        __syncthreads();
    }
    int i = blockIdx.x * blockDim.x + tid;
    if (i >= NN) return;
    int j = i >> 9;
    int off = (j == 0) ? 0 : sb[j - 1];
    int excl = g_tmp[i] - g_cnt[i] + off;
    g_rowptr[i] = excl;
    g_cnt[i]    = 0;                 // restore invariant: g_cnt==0 at next call
    if (i == NN - 1) g_rowptr[NN] = g_tmp[i] + off;
}
// atomic-free scatter: position = rowptr[dst] + rank (recorded by k_hist)
__global__ void k_scatter(const int* __restrict__ src, const int* __restrict__ dst) {
    pdl_wait();
    int e = blockIdx.x * blockDim.x + threadIdx.x;
    if (e >= EE) return;
    int d = dst[e];
    g_srcs[g_rowptr[d] + g_rank[e]] = src[e];
}

// ======================= fused edge-softmax + aggregation =======================
// one warp per dst node; fp16 feat gather (256 B/row = 32 uint2), fp32 accumulate,
// fp16 output (g_agg_h).
__global__ void __launch_bounds__(256)
gat_agg(const float* __restrict__ bias) {
    pdl_wait();
    __shared__ float2 s_ex[8][32];
    __shared__ int    s_src[8][32];
    int lane = threadIdx.x & 31, w = threadIdx.x >> 5;
    int d = blockIdx.x * 8 + w;
    if (d >= NN) return;
    int beg = g_rowptr[d], end = g_rowptr[d + 1];
    float2 er2 = *(const float2*)(g_er + 2 * d);
    const uint2* feath = (const uint2*)g_feat_h;

    float4 acc = make_float4(0.f, 0.f, 0.f, 0.f);
    float z0 = 0.f, z1 = 0.f;

    for (int c = beg; c < end; c += 32) {
        int idx = c + lane;
        bool valid = idx < end;
        int s = valid ? g_srcs[idx] : 0;
        float2 el2 = *(const float2*)(g_el + 2 * s);
        float e0 = el2.x + er2.x; e0 = e0 > 0.f ? e0 : 0.2f * e0;
        float e1 = el2.y + er2.y; e1 = e1 > 0.f ? e1 : 0.2f * e1;
        float x0 = valid ? __expf(e0) : 0.f;
        float x1 = valid ? __expf(e1) : 0.f;
        z0 += x0; z1 += x1;
        s_ex[w][lane]  = make_float2(x0, x1);
        s_src[w][lane] = s;
        __syncwarp();
        int m = min(32, end - c);
        #pragma unroll 4
        for (int j = 0; j < m; j++) {
            int sj = s_src[w][j];
            float2 exj = s_ex[w][j];
            float wgt = (lane < 16) ? exj.x : exj.y;
            uint2 u = feath[(size_t)sj * 32 + lane];
            float2 fa = __half22float2(*(const __half2*)&u.x);
            float2 fb = __half22float2(*(const __half2*)&u.y);
            acc.x = fmaf(wgt, fa.x, acc.x);
            acc.y = fmaf(wgt, fa.y, acc.y);
            acc.z = fmaf(wgt, fb.x, acc.z);
            acc.w = fmaf(wgt, fb.y, acc.w);
        }
        __syncwarp();
    }
    #pragma unroll
    for (int o = 16; o > 0; o >>= 1) {
        z0 += __shfl_xor_sync(0xffffffffu, z0, o);
        z1 += __shfl_xor_sync(0xffffffffu, z1, o);
    }
    float z = (lane < 16) ? z0 : z1;
    float ia = (z > 0.f) ? __fdividef(1.f, z) : 0.f;
    // bias for this lane's 4 cols (cols 4*lane .. 4*lane+3)
    float4 b4 = ((const float4*)bias)[lane];
    float4 o4;
    o4.x = fmaf(acc.x, ia, b4.x);
    o4.y = fmaf(acc.y, ia, b4.y);
    o4.z = fmaf(acc.z, ia, b4.z);
    o4.w = fmaf(acc.w, ia, b4.w);
    uint2 outw;
    *(__half2*)&outw.x = __floats2half2_rn(o4.x, o4.y);
    *(__half2*)&outw.y = __floats2half2_rn(o4.z, o4.w);
    ((uint2*)g_agg_h)[(size_t)d * 32 + lane] = outw;
}

// ======================= host =======================
template<typename... Args>
static inline void pdl_launch(dim3 gd, dim3 bd, void (*kfn)(Args...), Args... args) {
    cudaLaunchConfig_t cfg = {};
    cfg.gridDim = gd;
    cfg.blockDim = bd;
    cudaLaunchAttribute at[1];
    at[0].id = cudaLaunchAttributeProgrammaticStreamSerialization;
    at[0].val.programmaticStreamSerializationAllowed = 1;
    cfg.attrs = at;
    cfg.numAttrs = 1;
    cudaLaunchKernelEx(&cfg, kfn, args...);
}

extern "C" void kernel_launch(void* const* d_in, const int* in_sizes, int n_in,
                              void* d_out, int out_size) {
    const float* h     = (const float*)d_in[0];
    const int*   src   = (const int*)d_in[1];
    const int*   dst   = (const int*)d_in[2];
    const float* W1    = (const float*)d_in[3];
    const float* al1   = (const float*)d_in[4];
    const float* ar1   = (const float*)d_in[5];
    const float* b1    = (const float*)d_in[6];
    const float* lin1W = (const float*)d_in[7];
    const float* lin1b = (const float*)d_in[8];
    const float* W2    = (const float*)d_in[9];
    const float* al2   = (const float*)d_in[10];
    const float* ar2   = (const float*)d_in[11];
    const float* b2    = (const float*)d_in[12];
    const float* lin2W = (const float*)d_in[13];
    const float* lin2b = (const float*)d_in[14];
    float* out = (float*)d_out;

    void *aggp, *xp;
    cudaGetSymbolAddress(&aggp, g_agg_h);
    cudaGetSymbolAddress(&xp,   g_x_h);

    const int ROWT  = (NN + 127) / 128;           // 391
    const int NB    = (NN + 255) / 256;           // 196
    const int EB    = (EE + 255) / 256;           // 3125
    const int WARPB = (NN * 32 + 255) / 256;      // 6250

    const float* nfc = nullptr;
    void*        nv  = nullptr;

    // ---- layer-1 feat GEMM first (TRIG=true: fires early so k_hist overlaps) ----
    pdl_launch(dim3(ROWT, 2), dim3(256), gemm_mma<128, 128, true, true, false, false>,
               (const void*)h, W1, nfc, nv, (int)NN, 0, al1, ar1);

    // ---- CSR build (hist overlaps gemm1; rest is a dependent chain) ----
    pdl_launch(dim3(EB), dim3(256), k_hist, dst);
    pdl_launch(dim3(98), dim3(512), k_scan1);
    pdl_launch(dim3(NB), dim3(256), k_scan23);
    pdl_launch(dim3(EB), dim3(256), k_scatter, src, dst);

    // ---- layer 1 aggregation + lin ----
    pdl_launch(dim3(WARPB), dim3(256), gat_agg, b1);
    pdl_launch(dim3(ROWT, 1), dim3(256), gemm_mma<128, 64, false, false, true, true>,
               (const void*)aggp, lin1W, lin1b, xp, (int)NN, 1, nfc, nfc);

    // ---- layer 2 ----
    pdl_launch(dim3(ROWT, 2), dim3(256), gemm_mma<64, 128, true, false, true, false>,
               (const void*)xp, W2, nfc, nv, (int)NN, 0, al2, ar2);
    pdl_launch(dim3(WARPB), dim3(256), gat_agg, b2);
    pdl_launch(dim3(ROWT, 1), dim3(256), gemm_mma<128, 64, false, false, true, false>,
               (const void*)aggp, lin2W, lin2b, (void*)out, (int)NN, 0, nfc, nfc);
}